// round 3
// baseline (speedup 1.0000x reference)
#include <cuda_runtime.h>
#include <math.h>

#define NB    32
#define CH    512
#define WD    28
#define HDIM  28
#define NPIX  784
#define HEADS 8
#define DH    64

// Scratch (static __device__ — no allocations allowed)
__device__ float g_q[NB*CH*NPIX];      // [b][o][n]
__device__ float g_k[NB*CH*NPIX];      // [b][o][n]
__device__ float g_vT[NB*NPIX*CH];     // [b][n][o]
__device__ float g_pos[HEADS*DH*NPIX]; // [h*64+d][n]

// ---------------------------------------------------------------------------
__global__ void pos_kernel(const float* __restrict__ rel_h,
                           const float* __restrict__ rel_w) {
    int idx = blockIdx.x * 256 + threadIdx.x;
    if (idx >= HEADS*DH*NPIX) return;
    int n  = idx % NPIX;
    int hd = idx / NPIX;
    g_pos[idx] = rel_h[hd*HDIM + (n % HDIM)] + rel_w[hd*WD + (n / HDIM)];
}

// ---------------------------------------------------------------------------
// Projection GEMM: Y[o,n] = sum_c W[o,c] X[c,n] + bias[o], per batch.
// 128x128 tiles, K-chunk 16, 256 threads, 8x8 micro-tiles.
// ---------------------------------------------------------------------------
template<int WHICH>
__global__ void proj_kernel(const float* __restrict__ X,
                            const float* __restrict__ Wt,
                            const float* __restrict__ bias) {
    __shared__ float As[16][136];  // [c][o]
    __shared__ float Bs[16][136];  // [c][n]

    const int b  = blockIdx.z;
    const int o0 = blockIdx.y * 128;
    const int n0 = blockIdx.x * 128;
    const int tid = threadIdx.x;
    const int tx = tid & 15, ty = tid >> 4;
    const float* Xb = X + b*CH*NPIX;

    float acc[8][8] = {};

    for (int c0 = 0; c0 < CH; c0 += 16) {
        // A: 128 o x 16 c, transpose into As[c][o]
        {
            int c4 = (tid & 3) * 4;
            int ob = tid >> 2;
            #pragma unroll
            for (int io = 0; io < 2; io++) {
                int o = ob + io*64;
                float4 w = *(const float4*)&Wt[(o0+o)*CH + c0 + c4];
                As[c4+0][o] = w.x; As[c4+1][o] = w.y;
                As[c4+2][o] = w.z; As[c4+3][o] = w.w;
            }
        }
        // B: 16 c x 128 n
        {
            int n4 = (tid & 31) * 4;
            int cb = tid >> 5;
            int gn = n0 + n4;
            #pragma unroll
            for (int ic = 0; ic < 2; ic++) {
                int c = cb + ic*8;
                float4 v = {0.f,0.f,0.f,0.f};
                if (gn < NPIX) v = *(const float4*)&Xb[(c0+c)*NPIX + gn];
                *(float4*)&Bs[c][n4] = v;
            }
        }
        __syncthreads();
        #pragma unroll 8
        for (int kk = 0; kk < 16; kk++) {
            float4 a0 = *(const float4*)&As[kk][ty*8];
            float4 a1 = *(const float4*)&As[kk][ty*8+4];
            float4 b0 = *(const float4*)&Bs[kk][tx*8];
            float4 b1 = *(const float4*)&Bs[kk][tx*8+4];
            float ar[8] = {a0.x,a0.y,a0.z,a0.w,a1.x,a1.y,a1.z,a1.w};
            float br[8] = {b0.x,b0.y,b0.z,b0.w,b1.x,b1.y,b1.z,b1.w};
            #pragma unroll
            for (int r = 0; r < 8; r++)
                #pragma unroll
                for (int c = 0; c < 8; c++)
                    acc[r][c] += ar[r] * br[c];
        }
        __syncthreads();
    }

    if (WHICH < 2) {
        float* Y = (WHICH == 0) ? g_q : g_k;
        int n = n0 + tx*8;
        if (n < NPIX) {   // n mult of 8, NPIX mult of 8 -> whole 8-wide run valid
            #pragma unroll
            for (int r = 0; r < 8; r++) {
                int o = o0 + ty*8 + r;
                float bv = bias[o];
                float* dst = Y + (b*CH + o)*NPIX + n;
                float4 v0 = {acc[r][0]+bv, acc[r][1]+bv, acc[r][2]+bv, acc[r][3]+bv};
                float4 v1 = {acc[r][4]+bv, acc[r][5]+bv, acc[r][6]+bv, acc[r][7]+bv};
                *(float4*)dst = v0;
                *(float4*)(dst+4) = v1;
            }
        }
    } else {
        float br[8];
        #pragma unroll
        for (int r = 0; r < 8; r++) br[r] = bias[o0 + ty*8 + r];
        #pragma unroll
        for (int c = 0; c < 8; c++) {
            int n = n0 + tx*8 + c;
            if (n < NPIX) {
                float* dst = g_vT + (b*NPIX + n)*CH + o0 + ty*8;
                float4 v0 = {acc[0][c]+br[0], acc[1][c]+br[1],
                             acc[2][c]+br[2], acc[3][c]+br[3]};
                float4 v1 = {acc[4][c]+br[4], acc[5][c]+br[5],
                             acc[6][c]+br[6], acc[7][c]+br[7]};
                *(float4*)dst = v0;
                *(float4*)(dst+4) = v1;
            }
        }
    }
}

// ---------------------------------------------------------------------------
// Fused flash attention. Qe_i = [q_i ; pos_i], Ke_j = [k_j ; q_j] (128-dim).
// One block = one (b,h) x 128-query tile. 256 threads, 8x8 micro-tiles.
// ---------------------------------------------------------------------------
#define QE_OFF 0
#define KC_OFF 16896              // Qe: 128*132
#define VS_OFF (16896 + 4224)     // Kc: 32*132
#define PS_OFF (21120 + 9216)     // Vs: 128*72
#define ATTN_SMEM_FLOATS (30336 + 16896)   // + Ps: 128*132 = 47232 floats

__global__ void attn_kernel(float* __restrict__ out) {
    extern __shared__ float sm[];
    float* Qe = sm + QE_OFF;   // [dim 128][i 128] stride 132
    float* Kc = sm + KC_OFF;   // [dim 32][j 128] stride 132
    float* Vs = sm + VS_OFF;   // [j 128][d 64] stride 72
    float* Ps = sm + PS_OFF;   // [i 128][j 128] stride 132

    const int tid = threadIdx.x;
    const int tx = tid & 15, ty = tid >> 4;
    const int bh = blockIdx.y;
    const int b = bh >> 3, h = bh & 7;
    const int i0 = blockIdx.x * 128;

    const float* qb = g_q + (b*CH + h*DH)*NPIX;
    const float* kb = g_k + (b*CH + h*DH)*NPIX;
    const float* vb = g_vT + b*NPIX*CH + h*DH;
    const float* pb = g_pos + h*DH*NPIX;

    // Load Qe tile once: dims 0..63 = q, 64..127 = pos
    {
        int i4 = (tid & 31) * 4;
        int gi = i0 + i4;
        #pragma unroll
        for (int it = 0; it < 16; it++) {
            int dim = (tid >> 5) + it*8;
            float4 v = {0.f,0.f,0.f,0.f};
            if (gi < NPIX) {
                const float* src = (dim < DH) ? (qb + dim*NPIX)
                                              : (pb + (dim-DH)*NPIX);
                v = *(const float4*)(src + gi);
            }
            *(float4*)&Qe[dim*132 + i4] = v;
        }
    }

    float m[8], l[8], o_acc[8][4];
    #pragma unroll
    for (int r = 0; r < 8; r++) {
        m[r] = -INFINITY; l[r] = 0.f;
        #pragma unroll
        for (int c = 0; c < 4; c++) o_acc[r][c] = 0.f;
    }

    for (int jt = 0; jt < 7; jt++) {
        const int j0 = jt * 128;
        __syncthreads();  // protect Vs/Ps consumers of previous iteration

        // Vs[j][d]
        {
            int d4 = (tid & 15) * 4;
            #pragma unroll
            for (int it = 0; it < 8; it++) {
                int j = (tid >> 4) + it*16;
                int gj = j0 + j;
                float4 v = {0.f,0.f,0.f,0.f};
                if (gj < NPIX) v = *(const float4*)(vb + gj*CH + d4);
                *(float4*)&Vs[j*72 + d4] = v;
            }
        }

        float s[8][8] = {};
        for (int dc = 0; dc < 4; dc++) {
            __syncthreads();  // Kc reuse
            {
                int j4 = (tid & 31) * 4;
                int gj = j0 + j4;
                #pragma unroll
                for (int it = 0; it < 4; it++) {
                    int dim = (tid >> 5) + it*8;
                    int gdim = dc*32 + dim;
                    float4 v = {0.f,0.f,0.f,0.f};
                    if (gj < NPIX) {
                        const float* src = (gdim < DH) ? (kb + gdim*NPIX)
                                                       : (qb + (gdim-DH)*NPIX);
                        v = *(const float4*)(src + gj);
                    }
                    *(float4*)&Kc[dim*132 + j4] = v;
                }
            }
            __syncthreads();
            #pragma unroll 4
            for (int kk = 0; kk < 32; kk++) {
                float4 a0 = *(const float4*)&Qe[(dc*32+kk)*132 + ty*8];
                float4 a1 = *(const float4*)&Qe[(dc*32+kk)*132 + ty*8 + 4];
                float4 b0 = *(const float4*)&Kc[kk*132 + tx*8];
                float4 b1 = *(const float4*)&Kc[kk*132 + tx*8 + 4];
                float ar[8] = {a0.x,a0.y,a0.z,a0.w,a1.x,a1.y,a1.z,a1.w};
                float br[8] = {b0.x,b0.y,b0.z,b0.w,b1.x,b1.y,b1.z,b1.w};
                #pragma unroll
                for (int r = 0; r < 8; r++)
                    #pragma unroll
                    for (int c = 0; c < 8; c++)
                        s[r][c] += ar[r] * br[c];
            }
        }

        if (j0 + 128 > NPIX) {   // mask tail keys
            #pragma unroll
            for (int c = 0; c < 8; c++)
                if (j0 + tx*8 + c >= NPIX) {
                    #pragma unroll
                    for (int r = 0; r < 8; r++) s[r][c] = -INFINITY;
                }
        }

        // Online softmax; P stored row-major (float4 stores)
        #pragma unroll
        for (int r = 0; r < 8; r++) {
            float mx = s[r][0];
            #pragma unroll
            for (int c = 1; c < 8; c++) mx = fmaxf(mx, s[r][c]);
            #pragma unroll
            for (int off = 8; off > 0; off >>= 1)
                mx = fmaxf(mx, __shfl_xor_sync(0xffffffffu, mx, off));
            float mnew  = fmaxf(m[r], mx);
            float scale = __expf(m[r] - mnew);
            float p[8], rs = 0.f;
            #pragma unroll
            for (int c = 0; c < 8; c++) { p[c] = __expf(s[r][c] - mnew); rs += p[c]; }
            #pragma unroll
            for (int off = 8; off > 0; off >>= 1)
                rs += __shfl_xor_sync(0xffffffffu, rs, off);
            l[r] = l[r]*scale + rs;
            m[r] = mnew;
            #pragma unroll
            for (int c = 0; c < 4; c++) o_acc[r][c] *= scale;
            float4 p0 = {p[0],p[1],p[2],p[3]};
            float4 p1 = {p[4],p[5],p[6],p[7]};
            *(float4*)&Ps[(ty*8+r)*132 + tx*8]     = p0;
            *(float4*)&Ps[(ty*8+r)*132 + tx*8 + 4] = p1;
        }
        __syncthreads();

        // O += P @ V : thread owns O[i=ty*8+r][d=tx*4+c]
        #pragma unroll 2
        for (int j4 = 0; j4 < 32; j4++) {
            float4 v0 = *(const float4*)&Vs[(j4*4+0)*72 + tx*4];
            float4 v1 = *(const float4*)&Vs[(j4*4+1)*72 + tx*4];
            float4 v2 = *(const float4*)&Vs[(j4*4+2)*72 + tx*4];
            float4 v3 = *(const float4*)&Vs[(j4*4+3)*72 + tx*4];
            #pragma unroll
            for (int r = 0; r < 8; r++) {
                float4 pf = *(const float4*)&Ps[(ty*8+r)*132 + j4*4];
                o_acc[r][0] += pf.x*v0.x + pf.y*v1.x + pf.z*v2.x + pf.w*v3.x;
                o_acc[r][1] += pf.x*v0.y + pf.y*v1.y + pf.z*v2.y + pf.w*v3.y;
                o_acc[r][2] += pf.x*v0.z + pf.y*v1.z + pf.z*v2.z + pf.w*v3.z;
                o_acc[r][3] += pf.x*v0.w + pf.y*v1.w + pf.z*v2.w + pf.w*v3.w;
            }
        }
    }

    // Stage O in smem (reuse Qe region) then store coalesced.
    __syncthreads();
    float* Os = Qe;   // [d 64][i 128] stride 132
    #pragma unroll
    for (int r = 0; r < 8; r++) {
        float inv = __fdividef(1.f, l[r]);
        #pragma unroll
        for (int c = 0; c < 4; c++)
            Os[(tx*4+c)*132 + ty*8 + r] = o_acc[r][c] * inv;
    }
    __syncthreads();
    {
        int i4 = (tid & 31) * 4;
        int gi = i0 + i4;
        if (gi < NPIX) {
            #pragma unroll
            for (int it = 0; it < 8; it++) {
                int d = (tid >> 5) + it*8;
                float4 v = *(const float4*)&Os[d*132 + i4];
                *(float4*)&out[(b*CH + h*DH + d)*NPIX + gi] = v;
            }
        }
    }
}

// ---------------------------------------------------------------------------
extern "C" void kernel_launch(void* const* d_in, const int* in_sizes, int n_in,
                              void* d_out, int out_size) {
    const float* x     = (const float*)d_in[0];
    const float* wq    = (const float*)d_in[1];
    const float* bq    = (const float*)d_in[2];
    const float* wk    = (const float*)d_in[3];
    const float* bk    = (const float*)d_in[4];
    const float* wv    = (const float*)d_in[5];
    const float* bv    = (const float*)d_in[6];
    const float* rel_h = (const float*)d_in[7];
    const float* rel_w = (const float*)d_in[8];
    float* out = (float*)d_out;

    const int attn_smem = ATTN_SMEM_FLOATS * (int)sizeof(float);  // 188928 B
    cudaFuncSetAttribute(attn_kernel,
                         cudaFuncAttributeMaxDynamicSharedMemorySize, attn_smem);

    pos_kernel<<<(HEADS*DH*NPIX + 255)/256, 256>>>(rel_h, rel_w);

    dim3 pgrid(7, 4, NB);   // n-tiles x o-tiles x batch
    proj_kernel<0><<<pgrid, 256>>>(x, wq, bq);
    proj_kernel<1><<<pgrid, 256>>>(x, wk, bk);
    proj_kernel<2><<<pgrid, 256>>>(x, wv, bv);

    dim3 agrid(7, NB*HEADS);  // q-tiles x (b,h)
    attn_kernel<<<agrid, 256, attn_smem>>>(out);
}

// round 6
// speedup vs baseline: 1.7927x; 1.7927x over previous
#include <cuda_runtime.h>
#include <cuda_bf16.h>
#include <math.h>
#include <stdint.h>

#define NB    32
#define CH    512
#define WD    28
#define HDIM  28
#define NPIX  784
#define HEADS 8
#define DH    64

#if defined(__CUDA_ARCH__) && (defined(__CUDA_ARCH_FEAT_SM103_ALL) || defined(__CUDA_ARCH_FEAT_SM100_ALL))
#define HAS_TC 1
#else
#define HAS_TC 0
#endif

// ---------------- global scratch ----------------
__device__ float g_q[NB*CH*NPIX];       // [b][o][n]   (SIMT fallback)
__device__ float g_k[NB*CH*NPIX];
__device__ float g_vT[NB*NPIX*CH];      // [b][n][o]
__device__ float g_pos[HEADS*DH*NPIX];  // [h*64+d][n]
// bf16 hi/lo split operands for tensor path
__device__ __align__(16) __nv_bfloat16 g_qh[NB*NPIX*CH];   // [b][n][o]
__device__ __align__(16) __nv_bfloat16 g_ql[NB*NPIX*CH];
__device__ __align__(16) __nv_bfloat16 g_kh[NB*NPIX*CH];
__device__ __align__(16) __nv_bfloat16 g_kl[NB*NPIX*CH];
__device__ __align__(16) __nv_bfloat16 g_voh[NB*CH*NPIX];  // [b][o][n]  (V o-major)
__device__ __align__(16) __nv_bfloat16 g_vol[NB*CH*NPIX];
__device__ __align__(16) __nv_bfloat16 g_ph[HEADS*NPIX*DH];  // [h][n][d]
__device__ __align__(16) __nv_bfloat16 g_pl[HEADS*NPIX*DH];

// ---------------- helpers ----------------
__device__ __forceinline__ uint32_t smem_u32(const void* p) {
    uint32_t a;
    asm("{ .reg .u64 t; cvta.to.shared.u64 t, %1; cvt.u32.u64 %0, t; }"
        : "=r"(a) : "l"(p));
    return a;
}
__device__ __forceinline__ void split2(float a, float b, uint32_t& hi, uint32_t& lo) {
    __nv_bfloat16 ah = __float2bfloat16(a);
    __nv_bfloat16 bh = __float2bfloat16(b);
    __nv_bfloat16 al = __float2bfloat16(a - __bfloat162float(ah));
    __nv_bfloat16 bl = __float2bfloat16(b - __bfloat162float(bh));
    __nv_bfloat162 h2; h2.x = ah; h2.y = bh;
    __nv_bfloat162 l2; l2.x = al; l2.y = bl;
    hi = *(uint32_t*)&h2; lo = *(uint32_t*)&l2;
}

#if HAS_TC
__device__ __forceinline__ uint32_t elect1() {
    uint32_t p;
    asm volatile("{\n\t.reg .pred p;\n\telect.sync _|p, 0xFFFFFFFF;\n\t"
                 "selp.b32 %0, 1, 0, p;\n\t}" : "=r"(p));
    return p;
}
#define TC_ALLOC(sa, n)   asm volatile("tcgen05.alloc.cta_group::1.sync.aligned.shared::cta.b32 [%0], %1;" :: "r"(sa), "r"(n) : "memory")
#define TC_RELINQ()       asm volatile("tcgen05.relinquish_alloc_permit.cta_group::1.sync.aligned;")
#define TC_DEALLOC(t, n)  asm volatile("tcgen05.dealloc.cta_group::1.sync.aligned.b32 %0, %1;" :: "r"(t), "r"(n))
#define TC_COMMIT(mb)     asm volatile("tcgen05.commit.cta_group::1.mbarrier::arrive::one.shared::cluster.b64 [%0];" :: "r"(mb) : "memory")
#define TC_WAIT_LD()      asm volatile("tcgen05.wait::ld.sync.aligned;" ::: "memory")
#define TC_WAIT_ST()      asm volatile("tcgen05.wait::st.sync.aligned;" ::: "memory")
#define TC_FENCE_AFTER()  asm volatile("tcgen05.fence::after_thread_sync;" ::: "memory")
#define TC_FENCE_BEFORE() asm volatile("tcgen05.fence::before_thread_sync;" ::: "memory")
#define FENCE_ASYNC()     asm volatile("fence.proxy.async.shared::cta;" ::: "memory")
#define MBAR_INIT(mb, c)  asm volatile("mbarrier.init.shared.b64 [%0], %1;" :: "r"(mb), "r"(c) : "memory")

#define MBAR_WAIT(mb, par) do {                                              \
    uint32_t _mb = (mb); uint32_t _p = (par); uint32_t _done;                \
    asm volatile("{\n\t.reg .pred p;\n\t"                                    \
        "mbarrier.try_wait.parity.acquire.cta.shared::cta.b64 p, [%1], %2;\n\t" \
        "selp.b32 %0, 1, 0, p;\n\t}"                                         \
        : "=r"(_done) : "r"(_mb), "r"(_p) : "memory");                       \
    if (!_done) {                                                            \
        asm volatile("{\n\t.reg .pred P1;\n\t"                               \
            "WL_%=:\n\t"                                                     \
            "mbarrier.try_wait.parity.acquire.cta.shared::cta.b64 P1, [%0], %1, 0x989680;\n\t" \
            "@P1 bra.uni WD_%=;\n\tbra.uni WL_%=;\n\tWD_%=:\n\t}"            \
            :: "r"(_mb), "r"(_p) : "memory");                                \
    }                                                                        \
} while (0)

#define LDTM_X32(r, addr)                                                    \
    asm volatile("tcgen05.ld.sync.aligned.32x32b.x32.b32 "                   \
        "{%0,%1,%2,%3,%4,%5,%6,%7,%8,%9,%10,%11,%12,%13,%14,%15,"            \
        "%16,%17,%18,%19,%20,%21,%22,%23,%24,%25,%26,%27,%28,%29,%30,%31}, [%32];" \
        : "=r"((r)[0]),"=r"((r)[1]),"=r"((r)[2]),"=r"((r)[3]),               \
          "=r"((r)[4]),"=r"((r)[5]),"=r"((r)[6]),"=r"((r)[7]),               \
          "=r"((r)[8]),"=r"((r)[9]),"=r"((r)[10]),"=r"((r)[11]),             \
          "=r"((r)[12]),"=r"((r)[13]),"=r"((r)[14]),"=r"((r)[15]),           \
          "=r"((r)[16]),"=r"((r)[17]),"=r"((r)[18]),"=r"((r)[19]),           \
          "=r"((r)[20]),"=r"((r)[21]),"=r"((r)[22]),"=r"((r)[23]),           \
          "=r"((r)[24]),"=r"((r)[25]),"=r"((r)[26]),"=r"((r)[27]),           \
          "=r"((r)[28]),"=r"((r)[29]),"=r"((r)[30]),"=r"((r)[31])            \
        : "r"(addr))

#define STTM_X32(addr, r)                                                    \
    asm volatile("tcgen05.st.sync.aligned.32x32b.x32.b32 [%0], "             \
        "{%1,%2,%3,%4,%5,%6,%7,%8,%9,%10,%11,%12,%13,%14,%15,%16,"           \
        "%17,%18,%19,%20,%21,%22,%23,%24,%25,%26,%27,%28,%29,%30,%31,%32};"  \
        :: "r"(addr),                                                        \
           "r"((r)[0]),"r"((r)[1]),"r"((r)[2]),"r"((r)[3]),                  \
           "r"((r)[4]),"r"((r)[5]),"r"((r)[6]),"r"((r)[7]),                  \
           "r"((r)[8]),"r"((r)[9]),"r"((r)[10]),"r"((r)[11]),                \
           "r"((r)[12]),"r"((r)[13]),"r"((r)[14]),"r"((r)[15]),              \
           "r"((r)[16]),"r"((r)[17]),"r"((r)[18]),"r"((r)[19]),              \
           "r"((r)[20]),"r"((r)[21]),"r"((r)[22]),"r"((r)[23]),              \
           "r"((r)[24]),"r"((r)[25]),"r"((r)[26]),"r"((r)[27]),              \
           "r"((r)[28]),"r"((r)[29]),"r"((r)[30]),"r"((r)[31])               \
        : "memory")

// TS-mode f16 MMA (A in TMEM, B via SMEM descriptor) — test_mma_iter verified.
__device__ __forceinline__ void mma_f16_ts(uint32_t d, uint32_t a_tmem, uint64_t b,
                                           uint32_t idesc, bool acc) {
    uint32_t en = acc ? 1u : 0u;
    asm volatile("{\n\t.reg .pred p;\n\tsetp.ne.u32 p, %5, 0;\n\t"
        "tcgen05.mma.cta_group::1.kind::f16 [%0], [%1], %2, %3, {%4,%4,%4,%4}, p;\n\t}"
        :: "r"(d), "r"(a_tmem), "l"(b), "r"(idesc), "r"(0u), "r"(en) : "memory");
}
__device__ __forceinline__ uint64_t mkdesc_k(uint32_t addr) {   // SW128, LBO=1, SBO=64
    return ((2ull<<61)|(1ull<<46)|(64ull<<32)|(1ull<<16)) | ((uint64_t)(addr>>4)&0x3FFF);
}
// idesc kind::f16 (bf16 in, f32 acc): dtype<<4 | atype<<7 | btype<<10 | (N/8)<<17 | (M/16)<<24
#define IDESC_S  ((1u<<4)|(1u<<7)|(1u<<10)|((128/8)<<17)|((128/16)<<24))
#define IDESC_PV ((1u<<4)|(1u<<7)|(1u<<10)|((64/8)<<17)|((128/16)<<24))

// plain SW128 tile offset: rows of 128 bytes (test_mma / test_2cta layout)
__device__ __forceinline__ uint32_t sw_off(int row, int byte_in_row) {
    uint32_t off = (uint32_t)(row*128 + byte_in_row);
    return off ^ ((off >> 3) & 0x70);
}
#endif  // HAS_TC

// ---------------------------------------------------------------------------
__global__ void pos_kernel(const float* __restrict__ rel_h,
                           const float* __restrict__ rel_w) {
    int idx = blockIdx.x * 256 + threadIdx.x;
    if (idx >= HEADS*DH*NPIX) return;
    int n  = idx % NPIX;
    int hd = idx / NPIX;
    int h = hd >> 6, d = hd & 63;
    float v = rel_h[hd*HDIM + (n % HDIM)] + rel_w[hd*WD + (n / HDIM)];
    g_pos[idx] = v;
    __nv_bfloat16 hi = __float2bfloat16(v);
    size_t t = ((size_t)h*NPIX + n)*DH + d;
    g_ph[t] = hi;
    g_pl[t] = __float2bfloat16(v - __bfloat162float(hi));
}

// ---------------------------------------------------------------------------
// Projection GEMM. WHICH: 0=q, 1=k, 2=v.
// ---------------------------------------------------------------------------
template<int WHICH>
__global__ void proj_kernel(const float* __restrict__ X,
                            const float* __restrict__ Wt,
                            const float* __restrict__ bias) {
    __shared__ float As[16][136];
    __shared__ float Bs[16][136];

    const int bb = blockIdx.z;
    const int o0 = blockIdx.y * 128;
    const int n0 = blockIdx.x * 128;
    const int tid = threadIdx.x;
    const int tx = tid & 15, ty = tid >> 4;
    const float* Xb = X + (size_t)bb*CH*NPIX;

    float acc[8][8] = {};

    for (int c0 = 0; c0 < CH; c0 += 16) {
        {
            int c4 = (tid & 3) * 4;
            int ob = tid >> 2;
            #pragma unroll
            for (int io = 0; io < 2; io++) {
                int o = ob + io*64;
                float4 w = *(const float4*)&Wt[(o0+o)*CH + c0 + c4];
                As[c4+0][o] = w.x; As[c4+1][o] = w.y;
                As[c4+2][o] = w.z; As[c4+3][o] = w.w;
            }
        }
        {
            int n4 = (tid & 31) * 4;
            int cb = tid >> 5;
            int gn = n0 + n4;
            #pragma unroll
            for (int ic = 0; ic < 2; ic++) {
                int c = cb + ic*8;
                float4 v = {0.f,0.f,0.f,0.f};
                if (gn < NPIX) v = *(const float4*)&Xb[(c0+c)*NPIX + gn];
                *(float4*)&Bs[c][n4] = v;
            }
        }
        __syncthreads();
        #pragma unroll 8
        for (int kk = 0; kk < 16; kk++) {
            float4 a0 = *(const float4*)&As[kk][ty*8];
            float4 a1 = *(const float4*)&As[kk][ty*8+4];
            float4 b0 = *(const float4*)&Bs[kk][tx*8];
            float4 b1 = *(const float4*)&Bs[kk][tx*8+4];
            float ar[8] = {a0.x,a0.y,a0.z,a0.w,a1.x,a1.y,a1.z,a1.w};
            float br[8] = {b0.x,b0.y,b0.z,b0.w,b1.x,b1.y,b1.z,b1.w};
            #pragma unroll
            for (int r = 0; r < 8; r++)
                #pragma unroll
                for (int c = 0; c < 8; c++)
                    acc[r][c] += ar[r] * br[c];
        }
        __syncthreads();
    }

    #pragma unroll
    for (int r = 0; r < 8; r++) {
        float bv = bias[o0 + ty*8 + r];
        #pragma unroll
        for (int c = 0; c < 8; c++) acc[r][c] += bv;
    }

    if (WHICH < 2) {
        // fp32 [o][n] for SIMT fallback
        float* Y = (WHICH == 0) ? g_q : g_k;
        int n = n0 + tx*8;
        if (n < NPIX) {
            #pragma unroll
            for (int r = 0; r < 8; r++) {
                float* dst = Y + ((size_t)bb*CH + o0 + ty*8 + r)*NPIX + n;
                *(float4*)dst     = make_float4(acc[r][0],acc[r][1],acc[r][2],acc[r][3]);
                *(float4*)(dst+4) = make_float4(acc[r][4],acc[r][5],acc[r][6],acc[r][7]);
            }
        }
        // transposed bf16 hi/lo [n][o]
        __nv_bfloat16* OH = (WHICH == 0) ? g_qh : g_kh;
        __nv_bfloat16* OL = (WHICH == 0) ? g_ql : g_kl;
        #pragma unroll
        for (int c = 0; c < 8; c++) {
            int gn = n0 + tx*8 + c;
            if (gn < NPIX) {
                uint32_t h4[4], l4[4];
                #pragma unroll
                for (int rp = 0; rp < 4; rp++)
                    split2(acc[2*rp][c], acc[2*rp+1][c], h4[rp], l4[rp]);
                size_t dst = ((size_t)bb*NPIX + gn)*CH + o0 + ty*8;
                *(uint4*)&OH[dst] = make_uint4(h4[0],h4[1],h4[2],h4[3]);
                *(uint4*)&OL[dst] = make_uint4(l4[0],l4[1],l4[2],l4[3]);
            }
        }
    } else {
        // fp32 [n][o] for SIMT fallback
        #pragma unroll
        for (int c = 0; c < 8; c++) {
            int n = n0 + tx*8 + c;
            if (n < NPIX) {
                float* dst = g_vT + ((size_t)bb*NPIX + n)*CH + o0 + ty*8;
                *(float4*)dst     = make_float4(acc[0][c],acc[1][c],acc[2][c],acc[3][c]);
                *(float4*)(dst+4) = make_float4(acc[4][c],acc[5][c],acc[6][c],acc[7][c]);
            }
        }
        // o-major bf16 hi/lo [o][n] for TC path (V^T tiles)
        int n = n0 + tx*8;
        if (n < NPIX) {
            #pragma unroll
            for (int r = 0; r < 8; r++) {
                uint32_t h4[4], l4[4];
                #pragma unroll
                for (int cp = 0; cp < 4; cp++)
                    split2(acc[r][2*cp], acc[r][2*cp+1], h4[cp], l4[cp]);
                size_t dst = ((size_t)bb*CH + o0 + ty*8 + r)*NPIX + n;
                *(uint4*)&g_voh[dst] = make_uint4(h4[0],h4[1],h4[2],h4[3]);
                *(uint4*)&g_vol[dst] = make_uint4(l4[0],l4[1],l4[2],l4[3]);
            }
        }
    }
}

// ---------------------------------------------------------------------------
// Tensor-core flash attention, bf16x3 split, TS-mode MMAs only.
// TMEM cols: QH 0-63 | QL 64-127 | PH 128-191 | PL 192-255 | S 256-383 | O 384-447
// ---------------------------------------------------------------------------
#define OFF_K   1024                    /* 4 regions x 16KB: kh,kl,qh,ql (dims split) */
#define OFF_V   (OFF_K + 4*16384)       /* 4 regions x 8KB: vtAh,vtAl,vtBh,vtBl */
#define OFF_RED (OFF_V + 4*8192)
#define TC_SMEM (OFF_RED + 2048)        /* 100352 B */
#define TMC_QH 0
#define TMC_QL 64
#define TMC_PH 128
#define TMC_PL 192
#define TMC_S  256
#define TMC_O  384

__global__ __launch_bounds__(256, 1)
void attn_tc_kernel(float* __restrict__ out) {
#if HAS_TC
    extern __shared__ char smem[];
    const uint32_t sb = smem_u32(smem);
    const int tid = threadIdx.x;
    const int wid = tid >> 5, lid = tid & 31;
    const int chh = wid >> 2;                       // column half (0/1)
    const int irow = (wid & 3)*32 + lid;            // row via TMEM subpartition
    const uint32_t woff = (uint32_t)(wid & 3) << 21; // lane-block bits for tcgen05.st
    const int bh = blockIdx.y;
    const int bb = bh >> 3, h = bh & 7;
    const int i0 = blockIdx.x * 128;

    float* red = (float*)(smem + OFF_RED);

    if (wid == 0) { TC_ALLOC(sb + 0, 512); TC_RELINQ(); }
    if (tid == 0) MBAR_INIT(sb + 8, 1);
    __syncthreads();
    uint32_t tmem;
    asm volatile("ld.shared.b32 %0, [%1];" : "=r"(tmem) : "r"(sb + 0));

    const size_t bq = (size_t)bb*NPIX*CH + h*DH;    // base for [b][n][o] head slice
    const size_t bo = ((size_t)bb*CH + h*DH)*NPIX;  // base for [b][o][n] head slice

    // ---- store Qe (hi: warps 0-3, lo: warps 4-7) into TMEM ----
    {
        int gi = i0 + irow;
        uint32_t qr[32];
        const uint32_t* srcq = (chh == 0) ? (const uint32_t*)&g_qh[bq + (size_t)gi*CH]
                                          : (const uint32_t*)&g_ql[bq + (size_t)gi*CH];
        const uint32_t* srcp = (chh == 0) ? (const uint32_t*)&g_ph[((size_t)h*NPIX + gi)*DH]
                                          : (const uint32_t*)&g_pl[((size_t)h*NPIX + gi)*DH];
        uint32_t cb = (chh == 0) ? TMC_QH : TMC_QL;
        #pragma unroll
        for (int c = 0; c < 32; c++) qr[c] = (gi < NPIX) ? srcq[c] : 0u;
        STTM_X32(tmem + cb + woff, qr);
        #pragma unroll
        for (int c = 0; c < 32; c++) qr[c] = (gi < NPIX) ? srcp[c] : 0u;
        STTM_X32(tmem + cb + 32 + woff, qr);
        TC_WAIT_ST();
    }
    TC_FENCE_BEFORE();
    __syncthreads();

    float m = -INFINITY, l = 0.f;
    float o_acc[32];
    #pragma unroll
    for (int c = 0; c < 32; c++) o_acc[c] = 0.f;
    uint32_t phase = 0;

    for (int jt = 0; jt < 7; jt++) {
        const int j0 = jt * 128;
        __syncthreads();   // previous iter's MMAs done (mbar) & smem consumers done

        // ---- K tiles: 4 regions (kh, kl, qh, ql) x [128 j][64 dims] ----
        #pragma unroll
        for (int it = 0; it < 16; it++) {
            int lin = tid + it*256;          // 0..4095
            int reg = lin >> 10;             // 0..3
            int j   = (lin >> 3) & 127;
            int u   = lin & 7;               // uint4 within 128B row
            int gj  = j0 + j;
            uint4 v = make_uint4(0,0,0,0);
            if (gj < NPIX) {
                size_t rb = bq + (size_t)gj*CH;
                const __nv_bfloat16* src =
                    (reg == 0) ? &g_kh[rb] : (reg == 1) ? &g_kl[rb] :
                    (reg == 2) ? &g_qh[rb] : &g_ql[rb];
                v = *(const uint4*)(src + u*8);
            }
            *(uint4*)(smem + OFF_K + reg*16384 + sw_off(j, u*16)) = v;
        }
        // ---- V^T tiles: 4 regions (Ah, Al, Bh, Bl) x [64 d][64 j] ----
        #pragma unroll
        for (int it = 0; it < 8; it++) {
            int lin = tid + it*256;          // 0..2047
            int reg = lin >> 9;              // 0..3
            int d   = (lin >> 3) & 63;
            int u   = lin & 7;
            int jc  = reg >> 1;              // j chunk
            int hl  = reg & 1;               // hi/lo
            int gjs = j0 + jc*64 + u*8;
            uint4 v = make_uint4(0,0,0,0);
            const __nv_bfloat16* src = hl ? g_vol : g_voh;
            src += bo + (size_t)d*NPIX;
            if (gjs + 7 < NPIX) {
                v = *(const uint4*)(src + gjs);
            } else if (gjs < NPIX) {
                __nv_bfloat16 tmp[8];
                #pragma unroll
                for (int e = 0; e < 8; e++)
                    tmp[e] = (gjs + e < NPIX) ? src[gjs + e] : __float2bfloat16(0.f);
                v = *(const uint4*)tmp;
            }
            *(uint4*)(smem + OFF_V + reg*8192 + sw_off(d, u*16)) = v;
        }
        FENCE_ASYNC();
        __syncthreads();

        // ---- S = Qe @ Ke^T : TS mode, 8 K-steps x 3 split-MMAs ----
        if (wid == 0) {
            TC_FENCE_AFTER();
            if (elect1()) {
                #pragma unroll
                for (int s = 0; s < 8; s++) {
                    int chunk = s >> 2;
                    uint64_t bh_d = mkdesc_k(sb + OFF_K + chunk*32768) + (uint64_t)((s&3)*2);
                    uint64_t bl_d = mkdesc_k(sb + OFF_K + chunk*32768 + 16384) + (uint64_t)((s&3)*2);
                    uint32_t aH = tmem + TMC_QH + s*8;
                    uint32_t aL = tmem + TMC_QL + s*8;
                    mma_f16_ts(tmem + TMC_S, aH, bh_d, IDESC_S, s != 0);
                    mma_f16_ts(tmem + TMC_S, aH, bl_d, IDESC_S, true);
                    mma_f16_ts(tmem + TMC_S, aL, bh_d, IDESC_S, true);
                }
                TC_COMMIT(sb + 8);
            }
        }
        MBAR_WAIT(sb + 8, phase); phase ^= 1;
        TC_FENCE_AFTER();

        // ---- read this thread's S half-row, online softmax ----
        float sv[64];
        {
            uint32_t rr[32];
            LDTM_X32(rr, tmem + TMC_S + chh*64);
            TC_WAIT_LD();
            #pragma unroll
            for (int c = 0; c < 32; c++) sv[c] = __uint_as_float(rr[c]);
            LDTM_X32(rr, tmem + TMC_S + chh*64 + 32);
            TC_WAIT_LD();
            #pragma unroll
            for (int c = 0; c < 32; c++) sv[32+c] = __uint_as_float(rr[c]);
        }
        TC_FENCE_BEFORE();
        float mx = -INFINITY;
        #pragma unroll
        for (int c = 0; c < 64; c++) {
            if (j0 + chh*64 + c >= NPIX) sv[c] = -INFINITY;
            mx = fmaxf(mx, sv[c]);
        }
        red[chh*128 + irow] = mx;
        __syncthreads();
        float mnew = fmaxf(m, fmaxf(red[irow], red[128 + irow]));
        float scale = __expf(m - mnew);
        m = mnew;
        float psum = 0.f;
        #pragma unroll
        for (int c = 0; c < 64; c++) {
            float p = __expf(sv[c] - mnew);
            sv[c] = p;
            psum += p;
        }
        red[256 + chh*128 + irow] = psum;
        __syncthreads();
        l = l*scale + red[256 + irow] + red[256 + 128 + irow];

        // ---- store P (hi/lo split) into TMEM ----
        {
            uint32_t prh[32], prl[32];
            #pragma unroll
            for (int c = 0; c < 32; c++)
                split2(sv[2*c], sv[2*c+1], prh[c], prl[c]);
            STTM_X32(tmem + TMC_PH + chh*32 + woff, prh);
            STTM_X32(tmem + TMC_PL + chh*32 + woff, prl);
            TC_WAIT_ST();
        }
        TC_FENCE_BEFORE();
        __syncthreads();

        // ---- O_part = P @ V : TS mode, B = V^T K-major ----
        if (wid == 0) {
            TC_FENCE_AFTER();
            if (elect1()) {
                #pragma unroll
                for (int s = 0; s < 8; s++) {
                    int chunk = s >> 2;
                    uint64_t bh_d = mkdesc_k(sb + OFF_V + chunk*16384) + (uint64_t)((s&3)*2);
                    uint64_t bl_d = mkdesc_k(sb + OFF_V + chunk*16384 + 8192) + (uint64_t)((s&3)*2);
                    uint32_t aH = tmem + TMC_PH + s*8;
                    uint32_t aL = tmem + TMC_PL + s*8;
                    mma_f16_ts(tmem + TMC_O, aH, bh_d, IDESC_PV, s != 0);
                    mma_f16_ts(tmem + TMC_O, aH, bl_d, IDESC_PV, true);
                    mma_f16_ts(tmem + TMC_O, aL, bh_d, IDESC_PV, true);
                }
                TC_COMMIT(sb + 8);
            }
        }
        MBAR_WAIT(sb + 8, phase); phase ^= 1;
        TC_FENCE_AFTER();

        {
            uint32_t po[32];
            LDTM_X32(po, tmem + TMC_O + chh*32);
            TC_WAIT_LD();
            TC_FENCE_BEFORE();
            #pragma unroll
            for (int c = 0; c < 32; c++)
                o_acc[c] = o_acc[c]*scale + __uint_as_float(po[c]);
        }
    }

    // ---- epilogue: normalize, transpose via smem, coalesced store ----
    __syncthreads();
    float inv = __fdividef(1.f, l);
    float* Os = (float*)(smem + OFF_K);   // [d 64][i 128] stride 132
    #pragma unroll
    for (int c = 0; c < 32; c++)
        Os[(chh*32 + c)*132 + irow] = o_acc[c] * inv;
    __syncthreads();
    #pragma unroll
    for (int it = 0; it < 8; it++) {
        int lin = tid + it*256;
        int d = lin >> 5, i4 = (lin & 31)*4;
        int gi = i0 + i4;
        if (gi < NPIX) {
            float4 v = *(const float4*)&Os[d*132 + i4];
            *(float4*)&out[bo + (size_t)d*NPIX + gi] = v;
        }
    }
    __syncthreads();
    if (wid == 0) TC_DEALLOC(tmem, 512);
#else
    (void)out;
#endif
}

// ---------------------------------------------------------------------------
// SIMT fp32 flash attention fallback (body only on non-103a passes).
// ---------------------------------------------------------------------------
#define SQE_OFF 0
#define SKE_OFF (128*68)
#define SVS_OFF (2*128*68)
#define SPS_OFF (2*128*68 + 64*68)
#define SIMT_SMEM ((2*128*68 + 2*64*68) * 4)

__global__ void attn_simt_kernel(float* __restrict__ out) {
#if !HAS_TC
    extern __shared__ float sm[];
    float* Qe = sm + SQE_OFF;
    float* Ke = sm + SKE_OFF;
    float* Vs = sm + SVS_OFF;
    float* Ps = sm + SPS_OFF;

    const int tid = threadIdx.x;
    const int tx = tid & 15, ty = tid >> 4;
    const int bh = blockIdx.y;
    const int b = bh >> 3, h = bh & 7;
    const int i0 = blockIdx.x * 64;

    const float* qb = g_q + ((size_t)b*CH + h*DH)*NPIX;
    const float* kb = g_k + ((size_t)b*CH + h*DH)*NPIX;
    const float* vb = g_vT + (size_t)b*NPIX*CH + h*DH;
    const float* pb = g_pos + h*DH*NPIX;

    #pragma unroll
    for (int it = 0; it < 32; it++) {
        int idx = tid + it*256;
        int dim = idx >> 6, i = idx & 63;
        int gi = i0 + i;
        float v = 0.f;
        if (gi < NPIX)
            v = (dim < DH) ? qb[dim*NPIX + gi] : pb[(dim-DH)*NPIX + gi];
        Qe[dim*68 + i] = v;
    }

    float m[4], l[4], o_acc[4][4];
    #pragma unroll
    for (int r = 0; r < 4; r++) {
        m[r] = -INFINITY; l[r] = 0.f;
        #pragma unroll
        for (int c = 0; c < 4; c++) o_acc[r][c] = 0.f;
    }

    for (int jt = 0; jt < 13; jt++) {
        const int j0 = jt * 64;
        __syncthreads();

        #pragma unroll
        for (int it = 0; it < 32; it++) {
            int idx = tid + it*256;
            int dim = idx >> 6, j = idx & 63;
            int gj = j0 + j;
            float v = 0.f;
            if (gj < NPIX)
                v = (dim < DH) ? kb[dim*NPIX + gj] : qb[(dim-DH)*NPIX + gj];
            Ke[dim*68 + j] = v;
        }
        #pragma unroll
        for (int it = 0; it < 16; it++) {
            int idx = tid + it*256;
            int j = idx >> 6, d = idx & 63;
            int gj = j0 + j;
            Vs[j*68 + d] = (gj < NPIX) ? vb[(size_t)gj*CH + d] : 0.f;
        }
        __syncthreads();

        float s[4][4] = {};
        #pragma unroll 8
        for (int dim = 0; dim < 128; dim++) {
            float4 qf = *(const float4*)&Qe[dim*68 + ty*4];
            float4 kf = *(const float4*)&Ke[dim*68 + tx*4];
            float qr[4] = {qf.x, qf.y, qf.z, qf.w};
            float kr[4] = {kf.x, kf.y, kf.z, kf.w};
            #pragma unroll
            for (int r = 0; r < 4; r++)
                #pragma unroll
                for (int c = 0; c < 4; c++)
                    s[r][c] += qr[r] * kr[c];
        }

        if (j0 + 64 > NPIX) {
            #pragma unroll
            for (int c = 0; c < 4; c++)
                if (j0 + tx*4 + c >= NPIX) {
                    #pragma unroll
                    for (int r = 0; r < 4; r++) s[r][c] = -INFINITY;
                }
        }

        #pragma unroll
        for (int r = 0; r < 4; r++) {
            float mx = fmaxf(fmaxf(s[r][0], s[r][1]), fmaxf(s[r][2], s[r][3]));
            #pragma unroll
            for (int off = 8; off > 0; off >>= 1)
                mx = fmaxf(mx, __shfl_xor_sync(0xffffffffu, mx, off));
            float mnew  = fmaxf(m[r], mx);
            float scale = __expf(m[r] - mnew);
            float p0 = __expf(s[r][0] - mnew);
            float p1 = __expf(s[r][1] - mnew);
            float p2 = __expf(s[r][2] - mnew);
            float p3 = __expf(s[r][3] - mnew);
            float rs = (p0 + p1) + (p2 + p3);
            #pragma unroll
            for (int off = 8; off > 0; off >>= 1)
                rs += __shfl_xor_sync(0xffffffffu, rs, off);
            l[r] = l[r]*scale + rs;
            m[r] = mnew;
            #pragma unroll
            for (int c = 0; c < 4; c++) o_acc[r][c] *= scale;
            Ps[(tx*4+0)*68 + ty*4 + r] = p0;
            Ps[(tx*4+1)*68 + ty*4 + r] = p1;
            Ps[(tx*4+2)*68 + ty*4 + r] = p2;
            Ps[(tx*4+3)*68 + ty*4 + r] = p3;
        }
        __syncthreads();

        #pragma unroll 8
        for (int j = 0; j < 64; j++) {
            float4 pf = *(const float4*)&Ps[j*68 + ty*4];
            float4 vf = *(const float4*)&Vs[j*68 + tx*4];
            float pr[4] = {pf.x, pf.y, pf.z, pf.w};
            float vr[4] = {vf.x, vf.y, vf.z, vf.w};
            #pragma unroll
            for (int r = 0; r < 4; r++)
                #pragma unroll
                for (int c = 0; c < 4; c++)
                    o_acc[r][c] += pr[r] * vr[c];
        }
    }

    #pragma unroll
    for (int r = 0; r < 4; r++) {
        int i = i0 + ty*4 + r;
        if (i < NPIX) {
            float inv = __fdividef(1.f, l[r]);
            #pragma unroll
            for (int c = 0; c < 4; c++)
                out[((size_t)b*CH + h*DH + tx*4 + c)*NPIX + i] = o_acc[r][c] * inv;
        }
    }
#else
    (void)out;
#endif
}

// ---------------------------------------------------------------------------
extern "C" void kernel_launch(void* const* d_in, const int* in_sizes, int n_in,
                              void* d_out, int out_size) {
    const float* x     = (const float*)d_in[0];
    const float* wq    = (const float*)d_in[1];
    const float* bq    = (const float*)d_in[2];
    const float* wk    = (const float*)d_in[3];
    const float* bk    = (const float*)d_in[4];
    const float* wv    = (const float*)d_in[5];
    const float* bv    = (const float*)d_in[6];
    const float* rel_h = (const float*)d_in[7];
    const float* rel_w = (const float*)d_in[8];
    float* out = (float*)d_out;

    cudaFuncSetAttribute(attn_tc_kernel,
                         cudaFuncAttributeMaxDynamicSharedMemorySize, TC_SMEM);
    cudaFuncSetAttribute(attn_simt_kernel,
                         cudaFuncAttributeMaxDynamicSharedMemorySize, SIMT_SMEM);

    pos_kernel<<<(HEADS*DH*NPIX + 255)/256, 256>>>(rel_h, rel_w);

    dim3 pgrid(7, 4, NB);
    proj_kernel<0><<<pgrid, 256>>>(x, wq, bq);
    proj_kernel<1><<<pgrid, 256>>>(x, wk, bk);
    proj_kernel<2><<<pgrid, 256>>>(x, wv, bv);

    // Exactly one of these has a compiled body per gencode pass.
    dim3 tgrid(7, NB*HEADS);
    attn_tc_kernel<<<tgrid, 256, TC_SMEM>>>(out);
    dim3 sgrid(13, NB*HEADS);
    attn_simt_kernel<<<sgrid, 256, SIMT_SMEM>>>(out);
}

// round 8
// speedup vs baseline: 2.1292x; 1.1877x over previous
#include <cuda_runtime.h>
#include <cuda_bf16.h>
#include <math.h>
#include <stdint.h>

#define NB    32
#define CH    512
#define WD    28
#define HDIM  28
#define NPIX  784
#define HEADS 8
#define DH    64

#if defined(__CUDA_ARCH__) && (defined(__CUDA_ARCH_FEAT_SM103_ALL) || defined(__CUDA_ARCH_FEAT_SM100_ALL))
#define HAS_TC 1
#else
#define HAS_TC 0
#endif

// ---------------- global scratch (bf16 hi/lo split) ----------------
__device__ __align__(16) __nv_bfloat16 g_xh[NB*NPIX*CH];   // x^T [b][n][c]
__device__ __align__(16) __nv_bfloat16 g_xl[NB*NPIX*CH];
__device__ __align__(16) __nv_bfloat16 g_qh[NB*NPIX*CH];   // q^T [b][n][o]
__device__ __align__(16) __nv_bfloat16 g_ql[NB*NPIX*CH];
__device__ __align__(16) __nv_bfloat16 g_kh[NB*NPIX*CH];
__device__ __align__(16) __nv_bfloat16 g_kl[NB*NPIX*CH];
__device__ __align__(16) __nv_bfloat16 g_voh[NB*CH*NPIX];  // v [b][o][n]
__device__ __align__(16) __nv_bfloat16 g_vol[NB*CH*NPIX];
__device__ __align__(16) __nv_bfloat16 g_ph[HEADS*NPIX*DH]; // pos^T [h][n][d]
__device__ __align__(16) __nv_bfloat16 g_pl[HEADS*NPIX*DH];
__device__ __align__(16) __nv_bfloat16 g_wqh[CH*CH];       // W [o][c]
__device__ __align__(16) __nv_bfloat16 g_wql[CH*CH];
__device__ __align__(16) __nv_bfloat16 g_wkh[CH*CH];
__device__ __align__(16) __nv_bfloat16 g_wkl[CH*CH];
__device__ __align__(16) __nv_bfloat16 g_wvh[CH*CH];
__device__ __align__(16) __nv_bfloat16 g_wvl[CH*CH];

// ---------------- helpers ----------------
__device__ __forceinline__ uint32_t smem_u32(const void* p) {
    uint32_t a;
    asm("{ .reg .u64 t; cvta.to.shared.u64 t, %1; cvt.u32.u64 %0, t; }"
        : "=r"(a) : "l"(p));
    return a;
}
__device__ __forceinline__ void split2(float a, float b, uint32_t& hi, uint32_t& lo) {
    __nv_bfloat16 ah = __float2bfloat16(a);
    __nv_bfloat16 bh = __float2bfloat16(b);
    __nv_bfloat16 al = __float2bfloat16(a - __bfloat162float(ah));
    __nv_bfloat16 bl = __float2bfloat16(b - __bfloat162float(bh));
    __nv_bfloat162 h2; h2.x = ah; h2.y = bh;
    __nv_bfloat162 l2; l2.x = al; l2.y = bl;
    hi = *(uint32_t*)&h2; lo = *(uint32_t*)&l2;
}
__device__ __forceinline__ void split1(float a, __nv_bfloat16& hi, __nv_bfloat16& lo) {
    hi = __float2bfloat16(a);
    lo = __float2bfloat16(a - __bfloat162float(hi));
}

#if HAS_TC
__device__ __forceinline__ uint32_t elect1() {
    uint32_t p;
    asm volatile("{\n\t.reg .pred p;\n\telect.sync _|p, 0xFFFFFFFF;\n\t"
                 "selp.b32 %0, 1, 0, p;\n\t}" : "=r"(p));
    return p;
}
#define TC_ALLOC(sa, n)   asm volatile("tcgen05.alloc.cta_group::1.sync.aligned.shared::cta.b32 [%0], %1;" :: "r"(sa), "r"(n) : "memory")
#define TC_RELINQ()       asm volatile("tcgen05.relinquish_alloc_permit.cta_group::1.sync.aligned;")
#define TC_DEALLOC(t, n)  asm volatile("tcgen05.dealloc.cta_group::1.sync.aligned.b32 %0, %1;" :: "r"(t), "r"(n))
#define TC_COMMIT(mb)     asm volatile("tcgen05.commit.cta_group::1.mbarrier::arrive::one.shared::cluster.b64 [%0];" :: "r"(mb) : "memory")
#define TC_WAIT_LD()      asm volatile("tcgen05.wait::ld.sync.aligned;" ::: "memory")
#define TC_WAIT_ST()      asm volatile("tcgen05.wait::st.sync.aligned;" ::: "memory")
#define TC_FENCE_AFTER()  asm volatile("tcgen05.fence::after_thread_sync;" ::: "memory")
#define TC_FENCE_BEFORE() asm volatile("tcgen05.fence::before_thread_sync;" ::: "memory")
#define FENCE_ASYNC()     asm volatile("fence.proxy.async.shared::cta;" ::: "memory")
#define MBAR_INIT(mb, c)  asm volatile("mbarrier.init.shared.b64 [%0], %1;" :: "r"(mb), "r"(c) : "memory")

#define MBAR_WAIT(mb, par) do {                                              \
    uint32_t _mb = (mb); uint32_t _p = (par); uint32_t _done;                \
    asm volatile("{\n\t.reg .pred p;\n\t"                                    \
        "mbarrier.try_wait.parity.acquire.cta.shared::cta.b64 p, [%1], %2;\n\t" \
        "selp.b32 %0, 1, 0, p;\n\t}"                                         \
        : "=r"(_done) : "r"(_mb), "r"(_p) : "memory");                       \
    if (!_done) {                                                            \
        asm volatile("{\n\t.reg .pred P1;\n\t"                               \
            "WL_%=:\n\t"                                                     \
            "mbarrier.try_wait.parity.acquire.cta.shared::cta.b64 P1, [%0], %1, 0x989680;\n\t" \
            "@P1 bra.uni WD_%=;\n\tbra.uni WL_%=;\n\tWD_%=:\n\t}"            \
            :: "r"(_mb), "r"(_p) : "memory");                                \
    }                                                                        \
} while (0)

#define LDTM_X32(r, addr)                                                    \
    asm volatile("tcgen05.ld.sync.aligned.32x32b.x32.b32 "                   \
        "{%0,%1,%2,%3,%4,%5,%6,%7,%8,%9,%10,%11,%12,%13,%14,%15,"            \
        "%16,%17,%18,%19,%20,%21,%22,%23,%24,%25,%26,%27,%28,%29,%30,%31}, [%32];" \
        : "=r"((r)[0]),"=r"((r)[1]),"=r"((r)[2]),"=r"((r)[3]),               \
          "=r"((r)[4]),"=r"((r)[5]),"=r"((r)[6]),"=r"((r)[7]),               \
          "=r"((r)[8]),"=r"((r)[9]),"=r"((r)[10]),"=r"((r)[11]),             \
          "=r"((r)[12]),"=r"((r)[13]),"=r"((r)[14]),"=r"((r)[15]),           \
          "=r"((r)[16]),"=r"((r)[17]),"=r"((r)[18]),"=r"((r)[19]),           \
          "=r"((r)[20]),"=r"((r)[21]),"=r"((r)[22]),"=r"((r)[23]),           \
          "=r"((r)[24]),"=r"((r)[25]),"=r"((r)[26]),"=r"((r)[27]),           \
          "=r"((r)[28]),"=r"((r)[29]),"=r"((r)[30]),"=r"((r)[31])            \
        : "r"(addr))

#define STTM_X32(addr, r)                                                    \
    asm volatile("tcgen05.st.sync.aligned.32x32b.x32.b32 [%0], "             \
        "{%1,%2,%3,%4,%5,%6,%7,%8,%9,%10,%11,%12,%13,%14,%15,%16,"           \
        "%17,%18,%19,%20,%21,%22,%23,%24,%25,%26,%27,%28,%29,%30,%31,%32};"  \
        :: "r"(addr),                                                        \
           "r"((r)[0]),"r"((r)[1]),"r"((r)[2]),"r"((r)[3]),                  \
           "r"((r)[4]),"r"((r)[5]),"r"((r)[6]),"r"((r)[7]),                  \
           "r"((r)[8]),"r"((r)[9]),"r"((r)[10]),"r"((r)[11]),                \
           "r"((r)[12]),"r"((r)[13]),"r"((r)[14]),"r"((r)[15]),              \
           "r"((r)[16]),"r"((r)[17]),"r"((r)[18]),"r"((r)[19]),              \
           "r"((r)[20]),"r"((r)[21]),"r"((r)[22]),"r"((r)[23]),              \
           "r"((r)[24]),"r"((r)[25]),"r"((r)[26]),"r"((r)[27]),              \
           "r"((r)[28]),"r"((r)[29]),"r"((r)[30]),"r"((r)[31])               \
        : "memory")

__device__ __forceinline__ void mma_f16_ts(uint32_t d, uint32_t a_tmem, uint64_t b,
                                           uint32_t idesc, bool acc) {
    uint32_t en = acc ? 1u : 0u;
    asm volatile("{\n\t.reg .pred p;\n\tsetp.ne.u32 p, %5, 0;\n\t"
        "tcgen05.mma.cta_group::1.kind::f16 [%0], [%1], %2, %3, {%4,%4,%4,%4}, p;\n\t}"
        :: "r"(d), "r"(a_tmem), "l"(b), "r"(idesc), "r"(0u), "r"(en) : "memory");
}
__device__ __forceinline__ uint64_t mkdesc_k(uint32_t addr) {   // SW128, LBO=1, SBO=64
    return ((2ull<<61)|(1ull<<46)|(64ull<<32)|(1ull<<16)) | ((uint64_t)(addr>>4)&0x3FFF);
}
#define IDESC_128 ((1u<<4)|(1u<<7)|(1u<<10)|((128/8)<<17)|((128/16)<<24))
#define IDESC_64  ((1u<<4)|(1u<<7)|(1u<<10)|((64/8)<<17)|((128/16)<<24))

__device__ __forceinline__ uint32_t sw_off(int row, int byte_in_row) {
    uint32_t off = (uint32_t)(row*128 + byte_in_row);
    return off ^ ((off >> 3) & 0x70);
}
#endif  // HAS_TC

// ---------------------------------------------------------------------------
// Prep: pos split, x transpose+split, W split
// ---------------------------------------------------------------------------
__global__ void pos_kernel(const float* __restrict__ rel_h,
                           const float* __restrict__ rel_w) {
    int idx = blockIdx.x * 256 + threadIdx.x;
    if (idx >= HEADS*DH*NPIX) return;
    int n  = idx % NPIX;
    int hd = idx / NPIX;
    int h = hd >> 6, d = hd & 63;
    float v = rel_h[hd*HDIM + (n % HDIM)] + rel_w[hd*WD + (n / HDIM)];
    __nv_bfloat16 hi, lo;
    split1(v, hi, lo);
    size_t t = ((size_t)h*NPIX + n)*DH + d;
    g_ph[t] = hi; g_pl[t] = lo;
}

__global__ void split_x_kernel(const float* __restrict__ x) {
    __shared__ float t[32][33];
    const int bb = blockIdx.z;
    const int c0 = blockIdx.y * 32;
    const int n0 = blockIdx.x * 32;
    const int tx = threadIdx.x, ty = threadIdx.y;   // 32 x 8
    #pragma unroll
    for (int i = 0; i < 4; i++) {
        int c = c0 + ty + i*8;
        int n = n0 + tx;
        t[ty + i*8][tx] = (n < NPIX) ? x[((size_t)bb*CH + c)*NPIX + n] : 0.f;
    }
    __syncthreads();
    #pragma unroll
    for (int i = 0; i < 4; i++) {
        int n = n0 + ty + i*8;
        if (n < NPIX) {
            float v = t[tx][ty + i*8];
            __nv_bfloat16 hi, lo;
            split1(v, hi, lo);
            size_t d = ((size_t)bb*NPIX + n)*CH + c0 + tx;
            g_xh[d] = hi; g_xl[d] = lo;
        }
    }
}

__global__ void split_w_kernel(const float* __restrict__ wq,
                               const float* __restrict__ wk,
                               const float* __restrict__ wv) {
    int idx = blockIdx.x * 256 + threadIdx.x;
    if (idx >= 3*CH*CH) return;
    int m = idx / (CH*CH);
    int e = idx % (CH*CH);
    const float* src = (m == 0) ? wq : (m == 1) ? wk : wv;
    __nv_bfloat16* dh = (m == 0) ? g_wqh : (m == 1) ? g_wkh : g_wvh;
    __nv_bfloat16* dl = (m == 0) ? g_wql : (m == 1) ? g_wkl : g_wvl;
    __nv_bfloat16 hi, lo;
    split1(src[e], hi, lo);
    dh[e] = hi; dl[e] = lo;
}

// ---------------------------------------------------------------------------
// Tensor-core projection GEMM, bf16x3 split, TS mode.
// WHICH 0/1 (q/k): D[n][o] = X^T W^T   A = x^T rows (TMEM), B = W rows
// WHICH 2   (v):   D[o][n]             A = W rows (TMEM),  B = x^T rows
// TMEM cols: A0 0-63 (hi 0-31, lo 32-63) | A1 64-127 | D 128-255
// ---------------------------------------------------------------------------
#define PB_OFF 1024
#define PROJ_SMEM (PB_OFF + 4*16384)   /* 66560 B */

template<int WHICH>
__global__ __launch_bounds__(256, 2)
void proj_tc_kernel(const float* __restrict__ bias) {
#if HAS_TC
    extern __shared__ char smem[];
    const uint32_t sb = smem_u32(smem);
    const int tid = threadIdx.x;
    const int wid = tid >> 5, lid = tid & 31;
    const int chh = wid >> 2;
    const int irow = (wid & 3)*32 + lid;
    const uint32_t woff = (uint32_t)(wid & 3) << 21;
    const int bb = blockIdx.z;
    const int n0 = blockIdx.x * 128;
    const int o0 = blockIdx.y * 128;

    if (wid == 0) { TC_ALLOC(sb + 0, 256); TC_RELINQ(); }
    if (tid == 0) MBAR_INIT(sb + 8, 1);
    float* bias_s = (float*)(smem + 16);
    if (WHICH < 2 && tid < 128) bias_s[tid] = bias[o0 + tid];
    __syncthreads();
    uint32_t tmem;
    asm volatile("ld.shared.b32 %0, [%1];" : "=r"(tmem) : "r"(sb + 0));

    const size_t xb = (size_t)bb*NPIX*CH;
    const __nv_bfloat16 *Ah, *Al, *Bh, *Bl;
    int a_row, b_base;
    bool a_ok;
    if (WHICH < 2) {
        Ah = g_xh + xb; Al = g_xl + xb;
        Bh = (WHICH == 0) ? g_wqh : g_wkh;
        Bl = (WHICH == 0) ? g_wql : g_wkl;
        a_row = n0 + irow;  a_ok = (a_row < NPIX);  b_base = o0;
    } else {
        Ah = g_wvh; Al = g_wvl;
        Bh = g_xh + xb; Bl = g_xl + xb;
        a_row = o0 + irow;  a_ok = true;            b_base = n0;
    }

    const __nv_bfloat16* Asrc = chh ? Al : Ah;

    // ---- chunk loader: A row chunk -> TMEM, B 128-row chunk -> smem ----
    #define LOAD_CHUNK(ck) do {                                              \
        int _c0 = (ck)*64, _buf = (ck)&1;                                    \
        uint32_t ar[32];                                                     \
        const uint32_t* _as = (const uint32_t*)(Asrc + (size_t)a_row*CH + _c0); \
        _Pragma("unroll")                                                    \
        for (int c = 0; c < 32; c++) ar[c] = a_ok ? _as[c] : 0u;             \
        STTM_X32(tmem + _buf*64 + chh*32 + woff, ar);                        \
        TC_WAIT_ST();                                                        \
        int _r = tid & 127, _part = tid >> 7;                                \
        int _grow = b_base + _r;                                             \
        bool _ok = (WHICH < 2) ? true : (_grow < NPIX);                      \
        const uint4* _bs = (const uint4*)((_part ? Bl : Bh) + (size_t)_grow*CH + _c0); \
        uint32_t _dst = PB_OFF + _buf*32768 + _part*16384;                   \
        _Pragma("unroll")                                                    \
        for (int u = 0; u < 8; u++) {                                        \
            uint4 v = _ok ? _bs[u] : make_uint4(0,0,0,0);                    \
            *(uint4*)(smem + _dst + sw_off(_r, u*16)) = v;                   \
        }                                                                    \
    } while (0)

    LOAD_CHUNK(0);
    FENCE_ASYNC();
    TC_FENCE_BEFORE();
    __syncthreads();

    uint32_t phase = 0;
    for (int ck = 0; ck < 8; ck++) {
        int buf = ck & 1;
        if (wid == 0) {
            TC_FENCE_AFTER();
            if (elect1()) {
                uint64_t dh = mkdesc_k(sb + PB_OFF + buf*32768);
                uint64_t dl = mkdesc_k(sb + PB_OFF + buf*32768 + 16384);
                #pragma unroll
                for (int s = 0; s < 4; s++) {
                    uint32_t aH = tmem + buf*64 + s*8;
                    uint32_t aL = aH + 32;
                    mma_f16_ts(tmem + 128, aH, dh + s*2, IDESC_128, (ck > 0) || (s > 0));
                    mma_f16_ts(tmem + 128, aH, dl + s*2, IDESC_128, true);
                    mma_f16_ts(tmem + 128, aL, dh + s*2, IDESC_128, true);
                }
                TC_COMMIT(sb + 8);
            }
        }
        if (ck < 7) LOAD_CHUNK(ck + 1);
        FENCE_ASYNC();
        TC_FENCE_BEFORE();
        MBAR_WAIT(sb + 8, phase); phase ^= 1;
        __syncthreads();
    }
    #undef LOAD_CHUNK

    // ---- epilogue: D[irow][0..127] + bias -> split bf16 stores ----
    TC_FENCE_AFTER();
    float bv = (WHICH == 2) ? bias[a_row] : 0.f;
    #pragma unroll
    for (int half = 0; half < 2; half++) {
        float sv[64];
        {
            uint32_t rr[32];
            LDTM_X32(rr, tmem + 128 + half*64);
            TC_WAIT_LD();
            #pragma unroll
            for (int c = 0; c < 32; c++) sv[c] = __uint_as_float(rr[c]);
            LDTM_X32(rr, tmem + 128 + half*64 + 32);
            TC_WAIT_LD();
            #pragma unroll
            for (int c = 0; c < 32; c++) sv[32+c] = __uint_as_float(rr[c]);
        }
        if (WHICH < 2) {
            #pragma unroll
            for (int c = 0; c < 64; c++) sv[c] += bias_s[half*64 + c];
        } else {
            #pragma unroll
            for (int c = 0; c < 64; c++) sv[c] += bv;
        }
        uint32_t hw[32], lw[32];
        #pragma unroll
        for (int c = 0; c < 32; c++) split2(sv[2*c], sv[2*c+1], hw[c], lw[c]);

        if (WHICH < 2) {
            if (a_ok) {
                __nv_bfloat16* OH = (WHICH == 0) ? g_qh : g_kh;
                __nv_bfloat16* OL = (WHICH == 0) ? g_ql : g_kl;
                size_t d = xb + (size_t)a_row*CH + o0 + half*64;
                #pragma unroll
                for (int u = 0; u < 4; u++) {
                    *(uint4*)&OH[d + u*16]     = *(uint4*)&hw[u*8];
                    *(uint4*)&OH[d + u*16 + 8] = *(uint4*)&hw[u*8 + 4];
                    *(uint4*)&OL[d + u*16]     = *(uint4*)&lw[u*8];
                    *(uint4*)&OL[d + u*16 + 8] = *(uint4*)&lw[u*8 + 4];
                }
            }
        } else {
            size_t d = ((size_t)bb*CH + a_row)*NPIX + n0 + half*64;
            #pragma unroll
            for (int u = 0; u < 4; u++) {
                int gn = n0 + half*64 + u*16;
                if (gn < NPIX) {
                    *(uint4*)&g_voh[d + u*16] = *(uint4*)&hw[u*8];
                    *(uint4*)&g_vol[d + u*16] = *(uint4*)&lw[u*8];
                }
                if (gn + 8 < NPIX) {
                    *(uint4*)&g_voh[d + u*16 + 8] = *(uint4*)&hw[u*8 + 4];
                    *(uint4*)&g_vol[d + u*16 + 8] = *(uint4*)&lw[u*8 + 4];
                }
            }
        }
    }
    __syncthreads();
    if (wid == 0) TC_DEALLOC(tmem, 256);
#else
    (void)bias;
#endif
}

// ---------------------------------------------------------------------------
// Tensor-core flash attention (R6 passing version, unchanged).
// ---------------------------------------------------------------------------
#define OFF_K   1024
#define OFF_V   (OFF_K + 4*16384)
#define OFF_RED (OFF_V + 4*8192)
#define TC_SMEM (OFF_RED + 2048)
#define TMC_QH 0
#define TMC_QL 64
#define TMC_PH 128
#define TMC_PL 192
#define TMC_S  256
#define TMC_O  384

__global__ __launch_bounds__(256, 1)
void attn_tc_kernel(float* __restrict__ out) {
#if HAS_TC
    extern __shared__ char smem[];
    const uint32_t sb = smem_u32(smem);
    const int tid = threadIdx.x;
    const int wid = tid >> 5, lid = tid & 31;
    const int chh = wid >> 2;
    const int irow = (wid & 3)*32 + lid;
    const uint32_t woff = (uint32_t)(wid & 3) << 21;
    const int bh = blockIdx.y;
    const int bb = bh >> 3, h = bh & 7;
    const int i0 = blockIdx.x * 128;

    float* red = (float*)(smem + OFF_RED);

    if (wid == 0) { TC_ALLOC(sb + 0, 512); TC_RELINQ(); }
    if (tid == 0) MBAR_INIT(sb + 8, 1);
    __syncthreads();
    uint32_t tmem;
    asm volatile("ld.shared.b32 %0, [%1];" : "=r"(tmem) : "r"(sb + 0));

    const size_t bq = (size_t)bb*NPIX*CH + h*DH;
    const size_t bo = ((size_t)bb*CH + h*DH)*NPIX;

    {
        int gi = i0 + irow;
        uint32_t qr[32];
        const uint32_t* srcq = (chh == 0) ? (const uint32_t*)&g_qh[bq + (size_t)gi*CH]
                                          : (const uint32_t*)&g_ql[bq + (size_t)gi*CH];
        const uint32_t* srcp = (chh == 0) ? (const uint32_t*)&g_ph[((size_t)h*NPIX + gi)*DH]
                                          : (const uint32_t*)&g_pl[((size_t)h*NPIX + gi)*DH];
        uint32_t cb = (chh == 0) ? TMC_QH : TMC_QL;
        #pragma unroll
        for (int c = 0; c < 32; c++) qr[c] = (gi < NPIX) ? srcq[c] : 0u;
        STTM_X32(tmem + cb + woff, qr);
        #pragma unroll
        for (int c = 0; c < 32; c++) qr[c] = (gi < NPIX) ? srcp[c] : 0u;
        STTM_X32(tmem + cb + 32 + woff, qr);
        TC_WAIT_ST();
    }
    TC_FENCE_BEFORE();
    __syncthreads();

    float m = -INFINITY, l = 0.f;
    float o_acc[32];
    #pragma unroll
    for (int c = 0; c < 32; c++) o_acc[c] = 0.f;
    uint32_t phase = 0;

    for (int jt = 0; jt < 7; jt++) {
        const int j0 = jt * 128;
        __syncthreads();

        #pragma unroll
        for (int it = 0; it < 16; it++) {
            int lin = tid + it*256;
            int reg = lin >> 10;
            int j   = (lin >> 3) & 127;
            int u   = lin & 7;
            int gj  = j0 + j;
            uint4 v = make_uint4(0,0,0,0);
            if (gj < NPIX) {
                size_t rb = bq + (size_t)gj*CH;
                const __nv_bfloat16* src =
                    (reg == 0) ? &g_kh[rb] : (reg == 1) ? &g_kl[rb] :
                    (reg == 2) ? &g_qh[rb] : &g_ql[rb];
                v = *(const uint4*)(src + u*8);
            }
            *(uint4*)(smem + OFF_K + reg*16384 + sw_off(j, u*16)) = v;
        }
        #pragma unroll
        for (int it = 0; it < 8; it++) {
            int lin = tid + it*256;
            int reg = lin >> 9;
            int d   = (lin >> 3) & 63;
            int u   = lin & 7;
            int jc  = reg >> 1;
            int hl  = reg & 1;
            int gjs = j0 + jc*64 + u*8;
            uint4 v = make_uint4(0,0,0,0);
            const __nv_bfloat16* src = hl ? g_vol : g_voh;
            src += bo + (size_t)d*NPIX;
            if (gjs + 7 < NPIX) {
                v = *(const uint4*)(src + gjs);
            } else if (gjs < NPIX) {
                __nv_bfloat16 tmp[8];
                #pragma unroll
                for (int e = 0; e < 8; e++)
                    tmp[e] = (gjs + e < NPIX) ? src[gjs + e] : __float2bfloat16(0.f);
                v = *(const uint4*)tmp;
            }
            *(uint4*)(smem + OFF_V + reg*8192 + sw_off(d, u*16)) = v;
        }
        FENCE_ASYNC();
        __syncthreads();

        if (wid == 0) {
            TC_FENCE_AFTER();
            if (elect1()) {
                #pragma unroll
                for (int s = 0; s < 8; s++) {
                    int chunk = s >> 2;
                    uint64_t bh_d = mkdesc_k(sb + OFF_K + chunk*32768) + (uint64_t)((s&3)*2);
                    uint64_t bl_d = mkdesc_k(sb + OFF_K + chunk*32768 + 16384) + (uint64_t)((s&3)*2);
                    uint32_t aH = tmem + TMC_QH + s*8;
                    uint32_t aL = tmem + TMC_QL + s*8;
                    mma_f16_ts(tmem + TMC_S, aH, bh_d, IDESC_128, s != 0);
                    mma_f16_ts(tmem + TMC_S, aH, bl_d, IDESC_128, true);
                    mma_f16_ts(tmem + TMC_S, aL, bh_d, IDESC_128, true);
                }
                TC_COMMIT(sb + 8);
            }
        }
        MBAR_WAIT(sb + 8, phase); phase ^= 1;
        TC_FENCE_AFTER();

        float sv[64];
        {
            uint32_t rr[32];
            LDTM_X32(rr, tmem + TMC_S + chh*64);
            TC_WAIT_LD();
            #pragma unroll
            for (int c = 0; c < 32; c++) sv[c] = __uint_as_float(rr[c]);
            LDTM_X32(rr, tmem + TMC_S + chh*64 + 32);
            TC_WAIT_LD();
            #pragma unroll
            for (int c = 0; c < 32; c++) sv[32+c] = __uint_as_float(rr[c]);
        }
        TC_FENCE_BEFORE();
        float mx = -INFINITY;
        #pragma unroll
        for (int c = 0; c < 64; c++) {
            if (j0 + chh*64 + c >= NPIX) sv[c] = -INFINITY;
            mx = fmaxf(mx, sv[c]);
        }
        red[chh*128 + irow] = mx;
        __syncthreads();
        float mnew = fmaxf(m, fmaxf(red[irow], red[128 + irow]));
        float scale = __expf(m - mnew);
        m = mnew;
        float psum = 0.f;
        #pragma unroll
        for (int c = 0; c < 64; c++) {
            float p = __expf(sv[c] - mnew);
            sv[c] = p;
            psum += p;
        }
        red[256 + chh*128 + irow] = psum;
        __syncthreads();
        l = l*scale + red[256 + irow] + red[256 + 128 + irow];

        {
            uint32_t prh[32], prl[32];
            #pragma unroll
            for (int c = 0; c < 32; c++)
                split2(sv[2*c], sv[2*c+1], prh[c], prl[c]);
            STTM_X32(tmem + TMC_PH + chh*32 + woff, prh);
            STTM_X32(tmem + TMC_PL + chh*32 + woff, prl);
            TC_WAIT_ST();
        }
        TC_FENCE_BEFORE();
        __syncthreads();

        if (wid == 0) {
            TC_FENCE_AFTER();
            if (elect1()) {
                #pragma unroll
                for (int s = 0; s < 8; s++) {
                    int chunk = s >> 2;
                    uint64_t bh_d = mkdesc_k(sb + OFF_V + chunk*16384) + (uint64_t)((s&3)*2);
                    uint64_t bl_d = mkdesc_k(sb + OFF_V + chunk*16384 + 8192) + (uint64_t)((s&3)*2);
                    uint32_t aH = tmem + TMC_PH + s*8;
                    uint32_t aL = tmem + TMC_PL + s*8;
                    mma_f16_ts(tmem + TMC_O, aH, bh_d, IDESC_64, s != 0);
                    mma_f16_ts(tmem + TMC_O, aH, bl_d, IDESC_64, true);
                    mma_f16_ts(tmem + TMC_O, aL, bh_d, IDESC_64, true);
                }
                TC_COMMIT(sb + 8);
            }
        }
        MBAR_WAIT(sb + 8, phase); phase ^= 1;
        TC_FENCE_AFTER();

        {
            uint32_t po[32];
            LDTM_X32(po, tmem + TMC_O + chh*32);
            TC_WAIT_LD();
            TC_FENCE_BEFORE();
            #pragma unroll
            for (int c = 0; c < 32; c++)
                o_acc[c] = o_acc[c]*scale + __uint_as_float(po[c]);
        }
    }

    __syncthreads();
    float inv = __fdividef(1.f, l);
    float* Os = (float*)(smem + OFF_K);
    #pragma unroll
    for (int c = 0; c < 32; c++)
        Os[(chh*32 + c)*132 + irow] = o_acc[c] * inv;
    __syncthreads();
    #pragma unroll
    for (int it = 0; it < 8; it++) {
        int lin = tid + it*256;
        int d = lin >> 5, i4 = (lin & 31)*4;
        int gi = i0 + i4;
        if (gi < NPIX) {
            float4 v = *(const float4*)&Os[d*132 + i4];
            *(float4*)&out[bo + (size_t)d*NPIX + gi] = v;
        }
    }
    __syncthreads();
    if (wid == 0) TC_DEALLOC(tmem, 512);
#else
    (void)out;
#endif
}

// ---------------------------------------------------------------------------
extern "C" void kernel_launch(void* const* d_in, const int* in_sizes, int n_in,
                              void* d_out, int out_size) {
    const float* x     = (const float*)d_in[0];
    const float* wq    = (const float*)d_in[1];
    const float* bq    = (const float*)d_in[2];
    const float* wk    = (const float*)d_in[3];
    const float* bk    = (const float*)d_in[4];
    const float* wv    = (const float*)d_in[5];
    const float* bv    = (const float*)d_in[6];
    const float* rel_h = (const float*)d_in[7];
    const float* rel_w = (const float*)d_in[8];
    float* out = (float*)d_out;

    cudaFuncSetAttribute(attn_tc_kernel,
                         cudaFuncAttributeMaxDynamicSharedMemorySize, TC_SMEM);
    cudaFuncSetAttribute(proj_tc_kernel<0>,
                         cudaFuncAttributeMaxDynamicSharedMemorySize, PROJ_SMEM);
    cudaFuncSetAttribute(proj_tc_kernel<1>,
                         cudaFuncAttributeMaxDynamicSharedMemorySize, PROJ_SMEM);
    cudaFuncSetAttribute(proj_tc_kernel<2>,
                         cudaFuncAttributeMaxDynamicSharedMemorySize, PROJ_SMEM);

    // prep
    dim3 xgrid((NPIX + 31)/32, CH/32, NB);
    split_x_kernel<<<xgrid, dim3(32, 8)>>>(x);
    split_w_kernel<<<(3*CH*CH + 255)/256, 256>>>(wq, wk, wv);
    pos_kernel<<<(HEADS*DH*NPIX + 255)/256, 256>>>(rel_h, rel_w);

    // tcgen05 projections
    dim3 pgrid(7, 4, NB);
    proj_tc_kernel<0><<<pgrid, 256, PROJ_SMEM>>>(bq);
    proj_tc_kernel<1><<<pgrid, 256, PROJ_SMEM>>>(bk);
    proj_tc_kernel<2><<<pgrid, 256, PROJ_SMEM>>>(bv);

    // tcgen05 attention
    dim3 tgrid(7, NB*HEADS);
    attn_tc_kernel<<<tgrid, 256, TC_SMEM>>>(out);
}

// round 10
// speedup vs baseline: 2.8882x; 1.3565x over previous
#include <cuda_runtime.h>
#include <cuda_bf16.h>
#include <math.h>
#include <stdint.h>

#define NB    32
#define CH    512
#define WD    28
#define HDIM  28
#define NPIX  784
#define HEADS 8
#define DH    64

#if defined(__CUDA_ARCH__) && (defined(__CUDA_ARCH_FEAT_SM103_ALL) || defined(__CUDA_ARCH_FEAT_SM100_ALL))
#define HAS_TC 1
#else
#define HAS_TC 0
#endif

// ---------------- global scratch (bf16 hi/lo split) ----------------
__device__ __align__(16) __nv_bfloat16 g_xh[NB*NPIX*CH];   // x^T [b][n][c]
__device__ __align__(16) __nv_bfloat16 g_xl[NB*NPIX*CH];
__device__ __align__(16) __nv_bfloat16 g_qh[NB*NPIX*CH];   // q^T [b][n][o]
__device__ __align__(16) __nv_bfloat16 g_ql[NB*NPIX*CH];
__device__ __align__(16) __nv_bfloat16 g_kh[NB*NPIX*CH];
__device__ __align__(16) __nv_bfloat16 g_kl[NB*NPIX*CH];
__device__ __align__(16) __nv_bfloat16 g_voh[NB*CH*NPIX];  // v [b][o][n]
__device__ __align__(16) __nv_bfloat16 g_vol[NB*CH*NPIX];
__device__ __align__(16) __nv_bfloat16 g_ph[HEADS*NPIX*DH]; // pos^T [h][n][d]
__device__ __align__(16) __nv_bfloat16 g_pl[HEADS*NPIX*DH];
__device__ __align__(16) __nv_bfloat16 g_wqh[CH*CH];       // W [o][c]
__device__ __align__(16) __nv_bfloat16 g_wql[CH*CH];
__device__ __align__(16) __nv_bfloat16 g_wkh[CH*CH];
__device__ __align__(16) __nv_bfloat16 g_wkl[CH*CH];
__device__ __align__(16) __nv_bfloat16 g_wvh[CH*CH];
__device__ __align__(16) __nv_bfloat16 g_wvl[CH*CH];

// ---------------- helpers ----------------
__device__ __forceinline__ uint32_t smem_u32(const void* p) {
    uint32_t a;
    asm("{ .reg .u64 t; cvta.to.shared.u64 t, %1; cvt.u32.u64 %0, t; }"
        : "=r"(a) : "l"(p));
    return a;
}
__device__ __forceinline__ void split2(float a, float b, uint32_t& hi, uint32_t& lo) {
    __nv_bfloat16 ah = __float2bfloat16(a);
    __nv_bfloat16 bh = __float2bfloat16(b);
    __nv_bfloat16 al = __float2bfloat16(a - __bfloat162float(ah));
    __nv_bfloat16 bl = __float2bfloat16(b - __bfloat162float(bh));
    __nv_bfloat162 h2; h2.x = ah; h2.y = bh;
    __nv_bfloat162 l2; l2.x = al; l2.y = bl;
    hi = *(uint32_t*)&h2; lo = *(uint32_t*)&l2;
}
__device__ __forceinline__ void split1(float a, __nv_bfloat16& hi, __nv_bfloat16& lo) {
    hi = __float2bfloat16(a);
    lo = __float2bfloat16(a - __bfloat162float(hi));
}

#if HAS_TC
__device__ __forceinline__ uint32_t elect1() {
    uint32_t p;
    asm volatile("{\n\t.reg .pred p;\n\telect.sync _|p, 0xFFFFFFFF;\n\t"
                 "selp.b32 %0, 1, 0, p;\n\t}" : "=r"(p));
    return p;
}
#define TC_ALLOC(sa, n)   asm volatile("tcgen05.alloc.cta_group::1.sync.aligned.shared::cta.b32 [%0], %1;" :: "r"(sa), "r"(n) : "memory")
#define TC_RELINQ()       asm volatile("tcgen05.relinquish_alloc_permit.cta_group::1.sync.aligned;")
#define TC_DEALLOC(t, n)  asm volatile("tcgen05.dealloc.cta_group::1.sync.aligned.b32 %0, %1;" :: "r"(t), "r"(n))
#define TC_COMMIT(mb)     asm volatile("tcgen05.commit.cta_group::1.mbarrier::arrive::one.shared::cluster.b64 [%0];" :: "r"(mb) : "memory")
#define TC_WAIT_LD()      asm volatile("tcgen05.wait::ld.sync.aligned;" ::: "memory")
#define TC_WAIT_ST()      asm volatile("tcgen05.wait::st.sync.aligned;" ::: "memory")
#define TC_FENCE_AFTER()  asm volatile("tcgen05.fence::after_thread_sync;" ::: "memory")
#define TC_FENCE_BEFORE() asm volatile("tcgen05.fence::before_thread_sync;" ::: "memory")
#define FENCE_ASYNC()     asm volatile("fence.proxy.async.shared::cta;" ::: "memory")
#define MBAR_INIT(mb, c)  asm volatile("mbarrier.init.shared.b64 [%0], %1;" :: "r"(mb), "r"(c) : "memory")

#define MBAR_WAIT(mb, par) do {                                              \
    uint32_t _mb = (mb); uint32_t _p = (par); uint32_t _done;                \
    asm volatile("{\n\t.reg .pred p;\n\t"                                    \
        "mbarrier.try_wait.parity.acquire.cta.shared::cta.b64 p, [%1], %2;\n\t" \
        "selp.b32 %0, 1, 0, p;\n\t}"                                         \
        : "=r"(_done) : "r"(_mb), "r"(_p) : "memory");                       \
    if (!_done) {                                                            \
        asm volatile("{\n\t.reg .pred P1;\n\t"                               \
            "WL_%=:\n\t"                                                     \
            "mbarrier.try_wait.parity.acquire.cta.shared::cta.b64 P1, [%0], %1, 0x989680;\n\t" \
            "@P1 bra.uni WD_%=;\n\tbra.uni WL_%=;\n\tWD_%=:\n\t}"            \
            :: "r"(_mb), "r"(_p) : "memory");                                \
    }                                                                        \
} while (0)

#define LDTM_X32(r, addr)                                                    \
    asm volatile("tcgen05.ld.sync.aligned.32x32b.x32.b32 "                   \
        "{%0,%1,%2,%3,%4,%5,%6,%7,%8,%9,%10,%11,%12,%13,%14,%15,"            \
        "%16,%17,%18,%19,%20,%21,%22,%23,%24,%25,%26,%27,%28,%29,%30,%31}, [%32];" \
        : "=r"((r)[0]),"=r"((r)[1]),"=r"((r)[2]),"=r"((r)[3]),               \
          "=r"((r)[4]),"=r"((r)[5]),"=r"((r)[6]),"=r"((r)[7]),               \
          "=r"((r)[8]),"=r"((r)[9]),"=r"((r)[10]),"=r"((r)[11]),             \
          "=r"((r)[12]),"=r"((r)[13]),"=r"((r)[14]),"=r"((r)[15]),           \
          "=r"((r)[16]),"=r"((r)[17]),"=r"((r)[18]),"=r"((r)[19]),           \
          "=r"((r)[20]),"=r"((r)[21]),"=r"((r)[22]),"=r"((r)[23]),           \
          "=r"((r)[24]),"=r"((r)[25]),"=r"((r)[26]),"=r"((r)[27]),           \
          "=r"((r)[28]),"=r"((r)[29]),"=r"((r)[30]),"=r"((r)[31])            \
        : "r"(addr))

#define STTM_X32(addr, r)                                                    \
    asm volatile("tcgen05.st.sync.aligned.32x32b.x32.b32 [%0], "             \
        "{%1,%2,%3,%4,%5,%6,%7,%8,%9,%10,%11,%12,%13,%14,%15,%16,"           \
        "%17,%18,%19,%20,%21,%22,%23,%24,%25,%26,%27,%28,%29,%30,%31,%32};"  \
        :: "r"(addr),                                                        \
           "r"((r)[0]),"r"((r)[1]),"r"((r)[2]),"r"((r)[3]),                  \
           "r"((r)[4]),"r"((r)[5]),"r"((r)[6]),"r"((r)[7]),                  \
           "r"((r)[8]),"r"((r)[9]),"r"((r)[10]),"r"((r)[11]),                \
           "r"((r)[12]),"r"((r)[13]),"r"((r)[14]),"r"((r)[15]),              \
           "r"((r)[16]),"r"((r)[17]),"r"((r)[18]),"r"((r)[19]),              \
           "r"((r)[20]),"r"((r)[21]),"r"((r)[22]),"r"((r)[23]),              \
           "r"((r)[24]),"r"((r)[25]),"r"((r)[26]),"r"((r)[27]),              \
           "r"((r)[28]),"r"((r)[29]),"r"((r)[30]),"r"((r)[31])               \
        : "memory")

__device__ __forceinline__ void mma_f16_ts(uint32_t d, uint32_t a_tmem, uint64_t b,
                                           uint32_t idesc, bool acc) {
    uint32_t en = acc ? 1u : 0u;
    asm volatile("{\n\t.reg .pred p;\n\tsetp.ne.u32 p, %5, 0;\n\t"
        "tcgen05.mma.cta_group::1.kind::f16 [%0], [%1], %2, %3, {%4,%4,%4,%4}, p;\n\t}"
        :: "r"(d), "r"(a_tmem), "l"(b), "r"(idesc), "r"(0u), "r"(en) : "memory");
}
__device__ __forceinline__ uint64_t mkdesc_k(uint32_t addr) {   // SW128, LBO=1, SBO=64
    return ((2ull<<61)|(1ull<<46)|(64ull<<32)|(1ull<<16)) | ((uint64_t)(addr>>4)&0x3FFF);
}
#define IDESC_128 ((1u<<4)|(1u<<7)|(1u<<10)|((128/8)<<17)|((128/16)<<24))
#define IDESC_64  ((1u<<4)|(1u<<7)|(1u<<10)|((64/8)<<17)|((128/16)<<24))

__device__ __forceinline__ uint32_t sw_off(int row, int byte_in_row) {
    uint32_t off = (uint32_t)(row*128 + byte_in_row);
    return off ^ ((off >> 3) & 0x70);
}
#endif  // HAS_TC

// ---------------------------------------------------------------------------
// Prep kernels
// ---------------------------------------------------------------------------
__global__ void pos_kernel(const float* __restrict__ rel_h,
                           const float* __restrict__ rel_w) {
    int idx = blockIdx.x * 256 + threadIdx.x;
    if (idx >= HEADS*DH*NPIX) return;
    int n  = idx % NPIX;
    int hd = idx / NPIX;
    int h = hd >> 6, d = hd & 63;
    float v = rel_h[hd*HDIM + (n % HDIM)] + rel_w[hd*WD + (n / HDIM)];
    __nv_bfloat16 hi, lo;
    split1(v, hi, lo);
    size_t t = ((size_t)h*NPIX + n)*DH + d;
    g_ph[t] = hi; g_pl[t] = lo;
}

__global__ void split_x_kernel(const float* __restrict__ x) {
    __shared__ float t[32][33];
    const int bb = blockIdx.z;
    const int c0 = blockIdx.y * 32;
    const int n0 = blockIdx.x * 32;
    const int tx = threadIdx.x, ty = threadIdx.y;   // 32 x 8
    #pragma unroll
    for (int i = 0; i < 4; i++) {
        int c = c0 + ty + i*8;
        int n = n0 + tx;
        t[ty + i*8][tx] = (n < NPIX) ? x[((size_t)bb*CH + c)*NPIX + n] : 0.f;
    }
    __syncthreads();
    #pragma unroll
    for (int i = 0; i < 4; i++) {
        int n = n0 + ty + i*8;
        if (n < NPIX) {
            float v = t[tx][ty + i*8];
            __nv_bfloat16 hi, lo;
            split1(v, hi, lo);
            size_t d = ((size_t)bb*NPIX + n)*CH + c0 + tx;
            g_xh[d] = hi; g_xl[d] = lo;
        }
    }
}

__global__ void split_w_kernel(const float* __restrict__ wq,
                               const float* __restrict__ wk,
                               const float* __restrict__ wv) {
    int idx = blockIdx.x * 256 + threadIdx.x;
    if (idx >= 3*CH*CH) return;
    int m = idx / (CH*CH);
    int e = idx % (CH*CH);
    const float* src = (m == 0) ? wq : (m == 1) ? wk : wv;
    __nv_bfloat16* dh = (m == 0) ? g_wqh : (m == 1) ? g_wkh : g_wvh;
    __nv_bfloat16* dl = (m == 0) ? g_wql : (m == 1) ? g_wkl : g_wvl;
    __nv_bfloat16 hi, lo;
    split1(src[e], hi, lo);
    dh[e] = hi; dl[e] = lo;
}

// ---------------------------------------------------------------------------
// Merged QKV projection: one block = 128 n-rows x 128 o-cols x {q,k,v}.
// A = x rows (TMEM, shared by all 3), B = W_t rows (smem, 6 regions/chunk).
// TMEM: A double-buffer 0-127 | Dq 128-255 | Dk 256-383 | Dv 384-511.
// Two alternating mbarriers (A-B-A safe): commit ck -> mbar[ck&1],
// parity(ck) = (ck>>1)&1.
// ---------------------------------------------------------------------------
#define PB_OFF  2048
#define PCHUNK  98304                       /* 6 x 16KB */
#define PROJ_SMEM (PB_OFF + 2*PCHUNK)       /* 198656 B */
#define VT_STRIDE 136                       /* padded bf16 row for transpose */

__global__ __launch_bounds__(256, 1)
void qkv_tc_kernel(const float* __restrict__ bq,
                   const float* __restrict__ bk,
                   const float* __restrict__ bv) {
#if HAS_TC
    extern __shared__ char smem[];
    const uint32_t sb = smem_u32(smem);
    const int tid = threadIdx.x;
    const int wid = tid >> 5, lid = tid & 31;
    const int chh = wid >> 2;                 // 0 = hi plane, 1 = lo plane
    const int irow = (wid & 3)*32 + lid;      // n-row within tile
    const uint32_t woff = (uint32_t)(wid & 3) << 21;
    const int bb = blockIdx.z;
    const int n0 = blockIdx.x * 128;
    const int o0 = blockIdx.y * 128;

    if (wid == 0) { TC_ALLOC(sb + 0, 512); TC_RELINQ(); }
    if (tid == 0) { MBAR_INIT(sb + 8, 1); MBAR_INIT(sb + 16, 1); }
    float* bias_s = (float*)(smem + 64);      // [3][128]
    if (tid < 128) {
        bias_s[tid]       = bq[o0 + tid];
        bias_s[128 + tid] = bk[o0 + tid];
        bias_s[256 + tid] = bv[o0 + tid];
    }
    __syncthreads();
    uint32_t tmem;
    asm volatile("ld.shared.b32 %0, [%1];" : "=r"(tmem) : "r"(sb + 0));

    const size_t xb = (size_t)bb*NPIX*CH;
    const int a_row = n0 + irow;
    const bool a_ok = (a_row < NPIX);
    const __nv_bfloat16* Asrc = (chh ? g_xl : g_xh) + xb;

    // chunk loader: A 64-K chunk -> TMEM buf, B (3 outputs x 2 planes) -> smem buf
    #define LOADC(ck) do {                                                   \
        int _c0 = (ck)*64, _buf = (ck)&1;                                    \
        uint32_t ar[32];                                                     \
        const uint32_t* _as = (const uint32_t*)(Asrc + (size_t)a_row*CH + _c0); \
        _Pragma("unroll")                                                    \
        for (int c = 0; c < 32; c++) ar[c] = a_ok ? _as[c] : 0u;             \
        STTM_X32(tmem + _buf*64 + chh*32 + woff, ar);                        \
        TC_WAIT_ST();                                                        \
        _Pragma("unroll")                                                    \
        for (int it = 0; it < 24; it++) {                                    \
            int lin = tid + it*256;                                          \
            int reg = lin >> 10;                                             \
            int r   = (lin >> 3) & 127;                                      \
            int u   = lin & 7;                                               \
            const __nv_bfloat16* _src =                                      \
                (reg == 0) ? g_wqh : (reg == 1) ? g_wql :                    \
                (reg == 2) ? g_wkh : (reg == 3) ? g_wkl :                    \
                (reg == 4) ? g_wvh : g_wvl;                                  \
            uint4 v = *(const uint4*)(_src + (size_t)(o0 + r)*CH + _c0 + u*8); \
            *(uint4*)(smem + PB_OFF + _buf*PCHUNK + reg*16384 + sw_off(r, u*16)) = v; \
        }                                                                    \
    } while (0)

    LOADC(0);
    FENCE_ASYNC();
    TC_FENCE_BEFORE();
    __syncthreads();

    for (int ck = 0; ck < 8; ck++) {
        int buf = ck & 1;
        if (wid == 0) {
            TC_FENCE_AFTER();
            if (elect1()) {
                #pragma unroll
                for (int t = 0; t < 3; t++) {
                    uint32_t base = sb + PB_OFF + buf*PCHUNK + t*32768;
                    uint64_t dh = mkdesc_k(base);
                    uint64_t dl = mkdesc_k(base + 16384);
                    uint32_t D = tmem + 128 + t*128;
                    #pragma unroll
                    for (int s = 0; s < 4; s++) {
                        uint32_t aH = tmem + buf*64 + s*8;
                        uint32_t aL = aH + 32;
                        mma_f16_ts(D, aH, dh + s*2, IDESC_128, !(ck == 0 && s == 0));
                        mma_f16_ts(D, aH, dl + s*2, IDESC_128, true);
                        mma_f16_ts(D, aL, dh + s*2, IDESC_128, true);
                    }
                }
                TC_COMMIT(sb + 8 + (uint32_t)(ck & 1)*8);
            }
        }
        if (ck >= 1)   // wait for commit ck-1 on its own mbarrier (A-B-A safe)
            MBAR_WAIT(sb + 8 + (uint32_t)((ck - 1) & 1)*8, (uint32_t)(((ck - 1) >> 1) & 1));
        if (ck < 7) LOADC(ck + 1);
        FENCE_ASYNC();
        TC_FENCE_BEFORE();
        __syncthreads();
    }
    MBAR_WAIT(sb + 8 + 8, 1u);   // commit 7: mbar[1], parity (7>>1)&1 = 1
    #undef LOADC
    TC_FENCE_AFTER();

    // ---- epilogue ----
    __nv_bfloat16* vsm_h = (__nv_bfloat16*)(smem + PB_OFF);
    __nv_bfloat16* vsm_l = (__nv_bfloat16*)(smem + PB_OFF + 36864);

    #pragma unroll
    for (int t = 0; t < 3; t++) {
        float sv[64];
        {
            uint32_t rr[32];
            LDTM_X32(rr, tmem + 128 + t*128 + chh*64);
            TC_WAIT_LD();
            #pragma unroll
            for (int c = 0; c < 32; c++) sv[c] = __uint_as_float(rr[c]);
            LDTM_X32(rr, tmem + 128 + t*128 + chh*64 + 32);
            TC_WAIT_LD();
            #pragma unroll
            for (int c = 0; c < 32; c++) sv[32+c] = __uint_as_float(rr[c]);
        }
        #pragma unroll
        for (int c = 0; c < 64; c++) sv[c] += bias_s[t*128 + chh*64 + c];

        if (t < 2) {
            if (a_ok) {
                uint32_t hw[32], lw[32];
                #pragma unroll
                for (int c = 0; c < 32; c++) split2(sv[2*c], sv[2*c+1], hw[c], lw[c]);
                __nv_bfloat16* OH = (t == 0) ? g_qh : g_kh;
                __nv_bfloat16* OL = (t == 0) ? g_ql : g_kl;
                size_t d = xb + (size_t)a_row*CH + o0 + chh*64;
                #pragma unroll
                for (int u = 0; u < 4; u++) {
                    *(uint4*)&OH[d + u*16]     = *(uint4*)&hw[u*8];
                    *(uint4*)&OH[d + u*16 + 8] = *(uint4*)&hw[u*8 + 4];
                    *(uint4*)&OL[d + u*16]     = *(uint4*)&lw[u*8];
                    *(uint4*)&OL[d + u*16 + 8] = *(uint4*)&lw[u*8 + 4];
                }
            }
        } else {
            // v: transpose via smem (thread owns row n=irow, cols o=chh*64+c)
            __syncthreads();   // B buffers fully consumed — safe to reuse
            #pragma unroll
            for (int c = 0; c < 64; c++) {
                __nv_bfloat16 hi, lo;
                split1(sv[c], hi, lo);
                vsm_h[(chh*64 + c)*VT_STRIDE + irow] = hi;
                vsm_l[(chh*64 + c)*VT_STRIDE + irow] = lo;
            }
            __syncthreads();
            // coalesced store: thread -> (o = tid>>1, half = tid&1)
            int o = tid >> 1, half = tid & 1;
            size_t gdst = ((size_t)bb*CH + o0 + o)*NPIX + n0;
            #pragma unroll
            for (int u = 0; u < 8; u++) {
                int n = half*64 + u*8;
                if (n0 + n < NPIX) {
                    *(uint4*)&g_voh[gdst + n] = *(const uint4*)&vsm_h[o*VT_STRIDE + n];
                    *(uint4*)&g_vol[gdst + n] = *(const uint4*)&vsm_l[o*VT_STRIDE + n];
                }
            }
        }
    }
    __syncthreads();
    if (wid == 0) TC_DEALLOC(tmem, 512);
#else
    (void)bq; (void)bk; (void)bv;
#endif
}

// ---------------------------------------------------------------------------
// Tensor-core flash attention (R8 passing version, unchanged).
// ---------------------------------------------------------------------------
#define OFF_K   1024
#define OFF_V   (OFF_K + 4*16384)
#define OFF_RED (OFF_V + 4*8192)
#define TC_SMEM (OFF_RED + 2048)
#define TMC_QH 0
#define TMC_QL 64
#define TMC_PH 128
#define TMC_PL 192
#define TMC_S  256
#define TMC_O  384

__global__ __launch_bounds__(256, 1)
void attn_tc_kernel(float* __restrict__ out) {
#if HAS_TC
    extern __shared__ char smem[];
    const uint32_t sb = smem_u32(smem);
    const int tid = threadIdx.x;
    const int wid = tid >> 5, lid = tid & 31;
    const int chh = wid >> 2;
    const int irow = (wid & 3)*32 + lid;
    const uint32_t woff = (uint32_t)(wid & 3) << 21;
    const int bh = blockIdx.y;
    const int bb = bh >> 3, h = bh & 7;
    const int i0 = blockIdx.x * 128;

    float* red = (float*)(smem + OFF_RED);

    if (wid == 0) { TC_ALLOC(sb + 0, 512); TC_RELINQ(); }
    if (tid == 0) MBAR_INIT(sb + 8, 1);
    __syncthreads();
    uint32_t tmem;
    asm volatile("ld.shared.b32 %0, [%1];" : "=r"(tmem) : "r"(sb + 0));

    const size_t bq = (size_t)bb*NPIX*CH + h*DH;
    const size_t bo = ((size_t)bb*CH + h*DH)*NPIX;

    {
        int gi = i0 + irow;
        uint32_t qr[32];
        const uint32_t* srcq = (chh == 0) ? (const uint32_t*)&g_qh[bq + (size_t)gi*CH]
                                          : (const uint32_t*)&g_ql[bq + (size_t)gi*CH];
        const uint32_t* srcp = (chh == 0) ? (const uint32_t*)&g_ph[((size_t)h*NPIX + gi)*DH]
                                          : (const uint32_t*)&g_pl[((size_t)h*NPIX + gi)*DH];
        uint32_t cb = (chh == 0) ? TMC_QH : TMC_QL;
        #pragma unroll
        for (int c = 0; c < 32; c++) qr[c] = (gi < NPIX) ? srcq[c] : 0u;
        STTM_X32(tmem + cb + woff, qr);
        #pragma unroll
        for (int c = 0; c < 32; c++) qr[c] = (gi < NPIX) ? srcp[c] : 0u;
        STTM_X32(tmem + cb + 32 + woff, qr);
        TC_WAIT_ST();
    }
    TC_FENCE_BEFORE();
    __syncthreads();

    float m = -INFINITY, l = 0.f;
    float o_acc[32];
    #pragma unroll
    for (int c = 0; c < 32; c++) o_acc[c] = 0.f;
    uint32_t phase = 0;

    for (int jt = 0; jt < 7; jt++) {
        const int j0 = jt * 128;
        __syncthreads();

        #pragma unroll
        for (int it = 0; it < 16; it++) {
            int lin = tid + it*256;
            int reg = lin >> 10;
            int j   = (lin >> 3) & 127;
            int u   = lin & 7;
            int gj  = j0 + j;
            uint4 v = make_uint4(0,0,0,0);
            if (gj < NPIX) {
                size_t rb = bq + (size_t)gj*CH;
                const __nv_bfloat16* src =
                    (reg == 0) ? &g_kh[rb] : (reg == 1) ? &g_kl[rb] :
                    (reg == 2) ? &g_qh[rb] : &g_ql[rb];
                v = *(const uint4*)(src + u*8);
            }
            *(uint4*)(smem + OFF_K + reg*16384 + sw_off(j, u*16)) = v;
        }
        #pragma unroll
        for (int it = 0; it < 8; it++) {
            int lin = tid + it*256;
            int reg = lin >> 9;
            int d   = (lin >> 3) & 63;
            int u   = lin & 7;
            int jc  = reg >> 1;
            int hl  = reg & 1;
            int gjs = j0 + jc*64 + u*8;
            uint4 v = make_uint4(0,0,0,0);
            const __nv_bfloat16* src = hl ? g_vol : g_voh;
            src += bo + (size_t)d*NPIX;
            if (gjs + 7 < NPIX) {
                v = *(const uint4*)(src + gjs);
            } else if (gjs < NPIX) {
                __nv_bfloat16 tmp[8];
                #pragma unroll
                for (int e = 0; e < 8; e++)
                    tmp[e] = (gjs + e < NPIX) ? src[gjs + e] : __float2bfloat16(0.f);
                v = *(const uint4*)tmp;
            }
            *(uint4*)(smem + OFF_V + reg*8192 + sw_off(d, u*16)) = v;
        }
        FENCE_ASYNC();
        __syncthreads();

        if (wid == 0) {
            TC_FENCE_AFTER();
            if (elect1()) {
                #pragma unroll
                for (int s = 0; s < 8; s++) {
                    int chunk = s >> 2;
                    uint64_t bh_d = mkdesc_k(sb + OFF_K + chunk*32768) + (uint64_t)((s&3)*2);
                    uint64_t bl_d = mkdesc_k(sb + OFF_K + chunk*32768 + 16384) + (uint64_t)((s&3)*2);
                    uint32_t aH = tmem + TMC_QH + s*8;
                    uint32_t aL = tmem + TMC_QL + s*8;
                    mma_f16_ts(tmem + TMC_S, aH, bh_d, IDESC_128, s != 0);
                    mma_f16_ts(tmem + TMC_S, aH, bl_d, IDESC_128, true);
                    mma_f16_ts(tmem + TMC_S, aL, bh_d, IDESC_128, true);
                }
                TC_COMMIT(sb + 8);
            }
        }
        MBAR_WAIT(sb + 8, phase); phase ^= 1;
        TC_FENCE_AFTER();

        float sv[64];
        {
            uint32_t rr[32];
            LDTM_X32(rr, tmem + TMC_S + chh*64);
            TC_WAIT_LD();
            #pragma unroll
            for (int c = 0; c < 32; c++) sv[c] = __uint_as_float(rr[c]);
            LDTM_X32(rr, tmem + TMC_S + chh*64 + 32);
            TC_WAIT_LD();
            #pragma unroll
            for (int c = 0; c < 32; c++) sv[32+c] = __uint_as_float(rr[c]);
        }
        TC_FENCE_BEFORE();
        float mx = -INFINITY;
        #pragma unroll
        for (int c = 0; c < 64; c++) {
            if (j0 + chh*64 + c >= NPIX) sv[c] = -INFINITY;
            mx = fmaxf(mx, sv[c]);
        }
        red[chh*128 + irow] = mx;
        __syncthreads();
        float mnew = fmaxf(m, fmaxf(red[irow], red[128 + irow]));
        float scale = __expf(m - mnew);
        m = mnew;
        float psum = 0.f;
        #pragma unroll
        for (int c = 0; c < 64; c++) {
            float p = __expf(sv[c] - mnew);
            sv[c] = p;
            psum += p;
        }
        red[256 + chh*128 + irow] = psum;
        __syncthreads();
        l = l*scale + red[256 + irow] + red[256 + 128 + irow];

        {
            uint32_t prh[32], prl[32];
            #pragma unroll
            for (int c = 0; c < 32; c++)
                split2(sv[2*c], sv[2*c+1], prh[c], prl[c]);
            STTM_X32(tmem + TMC_PH + chh*32 + woff, prh);
            STTM_X32(tmem + TMC_PL + chh*32 + woff, prl);
            TC_WAIT_ST();
        }
        TC_FENCE_BEFORE();
        __syncthreads();

        if (wid == 0) {
            TC_FENCE_AFTER();
            if (elect1()) {
                #pragma unroll
                for (int s = 0; s < 8; s++) {
                    int chunk = s >> 2;
                    uint64_t bh_d = mkdesc_k(sb + OFF_V + chunk*16384) + (uint64_t)((s&3)*2);
                    uint64_t bl_d = mkdesc_k(sb + OFF_V + chunk*16384 + 8192) + (uint64_t)((s&3)*2);
                    uint32_t aH = tmem + TMC_PH + s*8;
                    uint32_t aL = tmem + TMC_PL + s*8;
                    mma_f16_ts(tmem + TMC_O, aH, bh_d, IDESC_64, s != 0);
                    mma_f16_ts(tmem + TMC_O, aH, bl_d, IDESC_64, true);
                    mma_f16_ts(tmem + TMC_O, aL, bh_d, IDESC_64, true);
                }
                TC_COMMIT(sb + 8);
            }
        }
        MBAR_WAIT(sb + 8, phase); phase ^= 1;
        TC_FENCE_AFTER();

        {
            uint32_t po[32];
            LDTM_X32(po, tmem + TMC_O + chh*32);
            TC_WAIT_LD();
            TC_FENCE_BEFORE();
            #pragma unroll
            for (int c = 0; c < 32; c++)
                o_acc[c] = o_acc[c]*scale + __uint_as_float(po[c]);
        }
    }

    __syncthreads();
    float inv = __fdividef(1.f, l);
    float* Os = (float*)(smem + OFF_K);
    #pragma unroll
    for (int c = 0; c < 32; c++)
        Os[(chh*32 + c)*132 + irow] = o_acc[c] * inv;
    __syncthreads();
    #pragma unroll
    for (int it = 0; it < 8; it++) {
        int lin = tid + it*256;
        int d = lin >> 5, i4 = (lin & 31)*4;
        int gi = i0 + i4;
        if (gi < NPIX) {
            float4 v = *(const float4*)&Os[d*132 + i4];
            *(float4*)&out[bo + (size_t)d*NPIX + gi] = v;
        }
    }
    __syncthreads();
    if (wid == 0) TC_DEALLOC(tmem, 512);
#else
    (void)out;
#endif
}

// ---------------------------------------------------------------------------
extern "C" void kernel_launch(void* const* d_in, const int* in_sizes, int n_in,
                              void* d_out, int out_size) {
    const float* x     = (const float*)d_in[0];
    const float* wq    = (const float*)d_in[1];
    const float* bq    = (const float*)d_in[2];
    const float* wk    = (const float*)d_in[3];
    const float* bk    = (const float*)d_in[4];
    const float* wv    = (const float*)d_in[5];
    const float* bv    = (const float*)d_in[6];
    const float* rel_h = (const float*)d_in[7];
    const float* rel_w = (const float*)d_in[8];
    float* out = (float*)d_out;

    cudaFuncSetAttribute(attn_tc_kernel,
                         cudaFuncAttributeMaxDynamicSharedMemorySize, TC_SMEM);
    cudaFuncSetAttribute(qkv_tc_kernel,
                         cudaFuncAttributeMaxDynamicSharedMemorySize, PROJ_SMEM);

    // prep
    dim3 xgrid((NPIX + 31)/32, CH/32, NB);
    split_x_kernel<<<xgrid, dim3(32, 8)>>>(x);
    split_w_kernel<<<(3*CH*CH + 255)/256, 256>>>(wq, wk, wv);
    pos_kernel<<<(HEADS*DH*NPIX + 255)/256, 256>>>(rel_h, rel_w);

    // merged tcgen05 QKV projection
    dim3 pgrid(7, 4, NB);
    qkv_tc_kernel<<<pgrid, 256, PROJ_SMEM>>>(bq, bk, bv);

    // tcgen05 attention
    dim3 tgrid(7, NB*HEADS);
    attn_tc_kernel<<<tgrid, 256, TC_SMEM>>>(out);
}

// round 11
// speedup vs baseline: 3.0664x; 1.0617x over previous
#include <cuda_runtime.h>
#include <cuda_bf16.h>
#include <math.h>
#include <stdint.h>

#define NB    32
#define CH    512
#define WD    28
#define HDIM  28
#define NPIX  784
#define HEADS 8
#define DH    64

#if defined(__CUDA_ARCH__) && (defined(__CUDA_ARCH_FEAT_SM103_ALL) || defined(__CUDA_ARCH_FEAT_SM100_ALL))
#define HAS_TC 1
#else
#define HAS_TC 0
#endif

// ---------------- global scratch (bf16 hi/lo split) ----------------
__device__ __align__(16) __nv_bfloat16 g_xh[NB*NPIX*CH];   // x^T [b][n][c]
__device__ __align__(16) __nv_bfloat16 g_xl[NB*NPIX*CH];
__device__ __align__(16) __nv_bfloat16 g_qh[NB*NPIX*CH];   // q^T [b][n][o]
__device__ __align__(16) __nv_bfloat16 g_ql[NB*NPIX*CH];
__device__ __align__(16) __nv_bfloat16 g_kh[NB*NPIX*CH];
__device__ __align__(16) __nv_bfloat16 g_kl[NB*NPIX*CH];
__device__ __align__(16) __nv_bfloat16 g_voh[NB*CH*NPIX];  // v [b][o][n]
__device__ __align__(16) __nv_bfloat16 g_vol[NB*CH*NPIX];
__device__ __align__(16) __nv_bfloat16 g_ph[HEADS*NPIX*DH]; // pos^T [h][n][d]
__device__ __align__(16) __nv_bfloat16 g_pl[HEADS*NPIX*DH];
__device__ __align__(16) __nv_bfloat16 g_wqh[CH*CH];       // W [o][c]
__device__ __align__(16) __nv_bfloat16 g_wql[CH*CH];
__device__ __align__(16) __nv_bfloat16 g_wkh[CH*CH];
__device__ __align__(16) __nv_bfloat16 g_wkl[CH*CH];
__device__ __align__(16) __nv_bfloat16 g_wvh[CH*CH];
__device__ __align__(16) __nv_bfloat16 g_wvl[CH*CH];

// ---------------- helpers ----------------
__device__ __forceinline__ uint32_t smem_u32(const void* p) {
    uint32_t a;
    asm("{ .reg .u64 t; cvta.to.shared.u64 t, %1; cvt.u32.u64 %0, t; }"
        : "=r"(a) : "l"(p));
    return a;
}
__device__ __forceinline__ void split2(float a, float b, uint32_t& hi, uint32_t& lo) {
    __nv_bfloat16 ah = __float2bfloat16(a);
    __nv_bfloat16 bh = __float2bfloat16(b);
    __nv_bfloat16 al = __float2bfloat16(a - __bfloat162float(ah));
    __nv_bfloat16 bl = __float2bfloat16(b - __bfloat162float(bh));
    __nv_bfloat162 h2; h2.x = ah; h2.y = bh;
    __nv_bfloat162 l2; l2.x = al; l2.y = bl;
    hi = *(uint32_t*)&h2; lo = *(uint32_t*)&l2;
}
__device__ __forceinline__ void split1(float a, __nv_bfloat16& hi, __nv_bfloat16& lo) {
    hi = __float2bfloat16(a);
    lo = __float2bfloat16(a - __bfloat162float(hi));
}

#if HAS_TC
__device__ __forceinline__ uint32_t elect1() {
    uint32_t p;
    asm volatile("{\n\t.reg .pred p;\n\telect.sync _|p, 0xFFFFFFFF;\n\t"
                 "selp.b32 %0, 1, 0, p;\n\t}" : "=r"(p));
    return p;
}
#define TC_ALLOC(sa, n)   asm volatile("tcgen05.alloc.cta_group::1.sync.aligned.shared::cta.b32 [%0], %1;" :: "r"(sa), "r"(n) : "memory")
#define TC_RELINQ()       asm volatile("tcgen05.relinquish_alloc_permit.cta_group::1.sync.aligned;")
#define TC_DEALLOC(t, n)  asm volatile("tcgen05.dealloc.cta_group::1.sync.aligned.b32 %0, %1;" :: "r"(t), "r"(n))
#define TC_COMMIT(mb)     asm volatile("tcgen05.commit.cta_group::1.mbarrier::arrive::one.shared::cluster.b64 [%0];" :: "r"(mb) : "memory")
#define TC_WAIT_LD()      asm volatile("tcgen05.wait::ld.sync.aligned;" ::: "memory")
#define TC_WAIT_ST()      asm volatile("tcgen05.wait::st.sync.aligned;" ::: "memory")
#define TC_FENCE_AFTER()  asm volatile("tcgen05.fence::after_thread_sync;" ::: "memory")
#define TC_FENCE_BEFORE() asm volatile("tcgen05.fence::before_thread_sync;" ::: "memory")
#define FENCE_ASYNC()     asm volatile("fence.proxy.async.shared::cta;" ::: "memory")
#define MBAR_INIT(mb, c)  asm volatile("mbarrier.init.shared.b64 [%0], %1;" :: "r"(mb), "r"(c) : "memory")

#define MBAR_WAIT(mb, par) do {                                              \
    uint32_t _mb = (mb); uint32_t _p = (par); uint32_t _done;                \
    asm volatile("{\n\t.reg .pred p;\n\t"                                    \
        "mbarrier.try_wait.parity.acquire.cta.shared::cta.b64 p, [%1], %2;\n\t" \
        "selp.b32 %0, 1, 0, p;\n\t}"                                         \
        : "=r"(_done) : "r"(_mb), "r"(_p) : "memory");                       \
    if (!_done) {                                                            \
        asm volatile("{\n\t.reg .pred P1;\n\t"                               \
            "WL_%=:\n\t"                                                     \
            "mbarrier.try_wait.parity.acquire.cta.shared::cta.b64 P1, [%0], %1, 0x989680;\n\t" \
            "@P1 bra.uni WD_%=;\n\tbra.uni WL_%=;\n\tWD_%=:\n\t}"            \
            :: "r"(_mb), "r"(_p) : "memory");                                \
    }                                                                        \
} while (0)

#define LDTM_X32(r, addr)                                                    \
    asm volatile("tcgen05.ld.sync.aligned.32x32b.x32.b32 "                   \
        "{%0,%1,%2,%3,%4,%5,%6,%7,%8,%9,%10,%11,%12,%13,%14,%15,"            \
        "%16,%17,%18,%19,%20,%21,%22,%23,%24,%25,%26,%27,%28,%29,%30,%31}, [%32];" \
        : "=r"((r)[0]),"=r"((r)[1]),"=r"((r)[2]),"=r"((r)[3]),               \
          "=r"((r)[4]),"=r"((r)[5]),"=r"((r)[6]),"=r"((r)[7]),               \
          "=r"((r)[8]),"=r"((r)[9]),"=r"((r)[10]),"=r"((r)[11]),             \
          "=r"((r)[12]),"=r"((r)[13]),"=r"((r)[14]),"=r"((r)[15]),           \
          "=r"((r)[16]),"=r"((r)[17]),"=r"((r)[18]),"=r"((r)[19]),           \
          "=r"((r)[20]),"=r"((r)[21]),"=r"((r)[22]),"=r"((r)[23]),           \
          "=r"((r)[24]),"=r"((r)[25]),"=r"((r)[26]),"=r"((r)[27]),           \
          "=r"((r)[28]),"=r"((r)[29]),"=r"((r)[30]),"=r"((r)[31])            \
        : "r"(addr))

#define STTM_X32(addr, r)                                                    \
    asm volatile("tcgen05.st.sync.aligned.32x32b.x32.b32 [%0], "             \
        "{%1,%2,%3,%4,%5,%6,%7,%8,%9,%10,%11,%12,%13,%14,%15,%16,"           \
        "%17,%18,%19,%20,%21,%22,%23,%24,%25,%26,%27,%28,%29,%30,%31,%32};"  \
        :: "r"(addr),                                                        \
           "r"((r)[0]),"r"((r)[1]),"r"((r)[2]),"r"((r)[3]),                  \
           "r"((r)[4]),"r"((r)[5]),"r"((r)[6]),"r"((r)[7]),                  \
           "r"((r)[8]),"r"((r)[9]),"r"((r)[10]),"r"((r)[11]),                \
           "r"((r)[12]),"r"((r)[13]),"r"((r)[14]),"r"((r)[15]),              \
           "r"((r)[16]),"r"((r)[17]),"r"((r)[18]),"r"((r)[19]),              \
           "r"((r)[20]),"r"((r)[21]),"r"((r)[22]),"r"((r)[23]),              \
           "r"((r)[24]),"r"((r)[25]),"r"((r)[26]),"r"((r)[27]),              \
           "r"((r)[28]),"r"((r)[29]),"r"((r)[30]),"r"((r)[31])               \
        : "memory")

__device__ __forceinline__ void mma_f16_ts(uint32_t d, uint32_t a_tmem, uint64_t b,
                                           uint32_t idesc, bool acc) {
    uint32_t en = acc ? 1u : 0u;
    asm volatile("{\n\t.reg .pred p;\n\tsetp.ne.u32 p, %5, 0;\n\t"
        "tcgen05.mma.cta_group::1.kind::f16 [%0], [%1], %2, %3, {%4,%4,%4,%4}, p;\n\t}"
        :: "r"(d), "r"(a_tmem), "l"(b), "r"(idesc), "r"(0u), "r"(en) : "memory");
}
__device__ __forceinline__ uint64_t mkdesc_k(uint32_t addr) {   // SW128, LBO=1, SBO=64
    return ((2ull<<61)|(1ull<<46)|(64ull<<32)|(1ull<<16)) | ((uint64_t)(addr>>4)&0x3FFF);
}
#define IDESC_128 ((1u<<4)|(1u<<7)|(1u<<10)|((128/8)<<17)|((128/16)<<24))
#define IDESC_64  ((1u<<4)|(1u<<7)|(1u<<10)|((64/8)<<17)|((128/16)<<24))

__device__ __forceinline__ uint32_t sw_off(int row, int byte_in_row) {
    uint32_t off = (uint32_t)(row*128 + byte_in_row);
    return off ^ ((off >> 3) & 0x70);
}
#endif  // HAS_TC

// ---------------------------------------------------------------------------
// Prep kernels
// ---------------------------------------------------------------------------
__global__ void pos_kernel(const float* __restrict__ rel_h,
                           const float* __restrict__ rel_w) {
    int idx = blockIdx.x * 256 + threadIdx.x;
    if (idx >= HEADS*DH*NPIX) return;
    int n  = idx % NPIX;
    int hd = idx / NPIX;
    int h = hd >> 6, d = hd & 63;
    float v = rel_h[hd*HDIM + (n % HDIM)] + rel_w[hd*WD + (n / HDIM)];
    __nv_bfloat16 hi, lo;
    split1(v, hi, lo);
    size_t t = ((size_t)h*NPIX + n)*DH + d;
    g_ph[t] = hi; g_pl[t] = lo;
}

__global__ void split_x_kernel(const float* __restrict__ x) {
    __shared__ float t[32][33];
    const int bb = blockIdx.z;
    const int c0 = blockIdx.y * 32;
    const int n0 = blockIdx.x * 32;
    const int tx = threadIdx.x, ty = threadIdx.y;   // 32 x 8
    #pragma unroll
    for (int i = 0; i < 4; i++) {
        int c = c0 + ty + i*8;
        int n = n0 + tx;
        t[ty + i*8][tx] = (n < NPIX) ? x[((size_t)bb*CH + c)*NPIX + n] : 0.f;
    }
    __syncthreads();
    #pragma unroll
    for (int i = 0; i < 4; i++) {
        int n = n0 + ty + i*8;
        if (n < NPIX) {
            float v = t[tx][ty + i*8];
            __nv_bfloat16 hi, lo;
            split1(v, hi, lo);
            size_t d = ((size_t)bb*NPIX + n)*CH + c0 + tx;
            g_xh[d] = hi; g_xl[d] = lo;
        }
    }
}

__global__ void split_w_kernel(const float* __restrict__ wq,
                               const float* __restrict__ wk,
                               const float* __restrict__ wv) {
    int idx = blockIdx.x * 256 + threadIdx.x;
    if (idx >= 3*CH*CH) return;
    int m = idx / (CH*CH);
    int e = idx % (CH*CH);
    const float* src = (m == 0) ? wq : (m == 1) ? wk : wv;
    __nv_bfloat16* dh = (m == 0) ? g_wqh : (m == 1) ? g_wkh : g_wvh;
    __nv_bfloat16* dl = (m == 0) ? g_wql : (m == 1) ? g_wkl : g_wvl;
    __nv_bfloat16 hi, lo;
    split1(src[e], hi, lo);
    dh[e] = hi; dl[e] = lo;
}

// ---------------------------------------------------------------------------
// Merged QKV projection (R10 passing version, unchanged).
// ---------------------------------------------------------------------------
#define PB_OFF  2048
#define PCHUNK  98304
#define PROJ_SMEM (PB_OFF + 2*PCHUNK)
#define VT_STRIDE 136

__global__ __launch_bounds__(256, 1)
void qkv_tc_kernel(const float* __restrict__ bq,
                   const float* __restrict__ bk,
                   const float* __restrict__ bv) {
#if HAS_TC
    extern __shared__ char smem[];
    const uint32_t sb = smem_u32(smem);
    const int tid = threadIdx.x;
    const int wid = tid >> 5, lid = tid & 31;
    const int chh = wid >> 2;
    const int irow = (wid & 3)*32 + lid;
    const uint32_t woff = (uint32_t)(wid & 3) << 21;
    const int bb = blockIdx.z;
    const int n0 = blockIdx.x * 128;
    const int o0 = blockIdx.y * 128;

    if (wid == 0) { TC_ALLOC(sb + 0, 512); TC_RELINQ(); }
    if (tid == 0) { MBAR_INIT(sb + 8, 1); MBAR_INIT(sb + 16, 1); }
    float* bias_s = (float*)(smem + 64);
    if (tid < 128) {
        bias_s[tid]       = bq[o0 + tid];
        bias_s[128 + tid] = bk[o0 + tid];
        bias_s[256 + tid] = bv[o0 + tid];
    }
    __syncthreads();
    uint32_t tmem;
    asm volatile("ld.shared.b32 %0, [%1];" : "=r"(tmem) : "r"(sb + 0));

    const size_t xb = (size_t)bb*NPIX*CH;
    const int a_row = n0 + irow;
    const bool a_ok = (a_row < NPIX);
    const __nv_bfloat16* Asrc = (chh ? g_xl : g_xh) + xb;

    #define LOADC(ck) do {                                                   \
        int _c0 = (ck)*64, _buf = (ck)&1;                                    \
        uint32_t ar[32];                                                     \
        const uint32_t* _as = (const uint32_t*)(Asrc + (size_t)a_row*CH + _c0); \
        _Pragma("unroll")                                                    \
        for (int c = 0; c < 32; c++) ar[c] = a_ok ? _as[c] : 0u;             \
        STTM_X32(tmem + _buf*64 + chh*32 + woff, ar);                        \
        TC_WAIT_ST();                                                        \
        _Pragma("unroll")                                                    \
        for (int it = 0; it < 24; it++) {                                    \
            int lin = tid + it*256;                                          \
            int reg = lin >> 10;                                             \
            int r   = (lin >> 3) & 127;                                      \
            int u   = lin & 7;                                               \
            const __nv_bfloat16* _src =                                      \
                (reg == 0) ? g_wqh : (reg == 1) ? g_wql :                    \
                (reg == 2) ? g_wkh : (reg == 3) ? g_wkl :                    \
                (reg == 4) ? g_wvh : g_wvl;                                  \
            uint4 v = *(const uint4*)(_src + (size_t)(o0 + r)*CH + _c0 + u*8); \
            *(uint4*)(smem + PB_OFF + _buf*PCHUNK + reg*16384 + sw_off(r, u*16)) = v; \
        }                                                                    \
    } while (0)

    LOADC(0);
    FENCE_ASYNC();
    TC_FENCE_BEFORE();
    __syncthreads();

    for (int ck = 0; ck < 8; ck++) {
        int buf = ck & 1;
        if (wid == 0) {
            TC_FENCE_AFTER();
            if (elect1()) {
                #pragma unroll
                for (int t = 0; t < 3; t++) {
                    uint32_t base = sb + PB_OFF + buf*PCHUNK + t*32768;
                    uint64_t dh = mkdesc_k(base);
                    uint64_t dl = mkdesc_k(base + 16384);
                    uint32_t D = tmem + 128 + t*128;
                    #pragma unroll
                    for (int s = 0; s < 4; s++) {
                        uint32_t aH = tmem + buf*64 + s*8;
                        uint32_t aL = aH + 32;
                        mma_f16_ts(D, aH, dh + s*2, IDESC_128, !(ck == 0 && s == 0));
                        mma_f16_ts(D, aH, dl + s*2, IDESC_128, true);
                        mma_f16_ts(D, aL, dh + s*2, IDESC_128, true);
                    }
                }
                TC_COMMIT(sb + 8 + (uint32_t)(ck & 1)*8);
            }
        }
        if (ck >= 1)
            MBAR_WAIT(sb + 8 + (uint32_t)((ck - 1) & 1)*8, (uint32_t)(((ck - 1) >> 1) & 1));
        if (ck < 7) LOADC(ck + 1);
        FENCE_ASYNC();
        TC_FENCE_BEFORE();
        __syncthreads();
    }
    MBAR_WAIT(sb + 8 + 8, 1u);
    #undef LOADC
    TC_FENCE_AFTER();

    __nv_bfloat16* vsm_h = (__nv_bfloat16*)(smem + PB_OFF);
    __nv_bfloat16* vsm_l = (__nv_bfloat16*)(smem + PB_OFF + 36864);

    #pragma unroll
    for (int t = 0; t < 3; t++) {
        float sv[64];
        {
            uint32_t rr[32];
            LDTM_X32(rr, tmem + 128 + t*128 + chh*64);
            TC_WAIT_LD();
            #pragma unroll
            for (int c = 0; c < 32; c++) sv[c] = __uint_as_float(rr[c]);
            LDTM_X32(rr, tmem + 128 + t*128 + chh*64 + 32);
            TC_WAIT_LD();
            #pragma unroll
            for (int c = 0; c < 32; c++) sv[32+c] = __uint_as_float(rr[c]);
        }
        #pragma unroll
        for (int c = 0; c < 64; c++) sv[c] += bias_s[t*128 + chh*64 + c];

        if (t < 2) {
            if (a_ok) {
                uint32_t hw[32], lw[32];
                #pragma unroll
                for (int c = 0; c < 32; c++) split2(sv[2*c], sv[2*c+1], hw[c], lw[c]);
                __nv_bfloat16* OH = (t == 0) ? g_qh : g_kh;
                __nv_bfloat16* OL = (t == 0) ? g_ql : g_kl;
                size_t d = xb + (size_t)a_row*CH + o0 + chh*64;
                #pragma unroll
                for (int u = 0; u < 4; u++) {
                    *(uint4*)&OH[d + u*16]     = *(uint4*)&hw[u*8];
                    *(uint4*)&OH[d + u*16 + 8] = *(uint4*)&hw[u*8 + 4];
                    *(uint4*)&OL[d + u*16]     = *(uint4*)&lw[u*8];
                    *(uint4*)&OL[d + u*16 + 8] = *(uint4*)&lw[u*8 + 4];
                }
            }
        } else {
            __syncthreads();
            #pragma unroll
            for (int c = 0; c < 64; c++) {
                __nv_bfloat16 hi, lo;
                split1(sv[c], hi, lo);
                vsm_h[(chh*64 + c)*VT_STRIDE + irow] = hi;
                vsm_l[(chh*64 + c)*VT_STRIDE + irow] = lo;
            }
            __syncthreads();
            int o = tid >> 1, half = tid & 1;
            size_t gdst = ((size_t)bb*CH + o0 + o)*NPIX + n0;
            #pragma unroll
            for (int u = 0; u < 8; u++) {
                int n = half*64 + u*8;
                if (n0 + n < NPIX) {
                    *(uint4*)&g_voh[gdst + n] = *(const uint4*)&vsm_h[o*VT_STRIDE + n];
                    *(uint4*)&g_vol[gdst + n] = *(const uint4*)&vsm_l[o*VT_STRIDE + n];
                }
            }
        }
    }
    __syncthreads();
    if (wid == 0) TC_DEALLOC(tmem, 512);
#else
    (void)bq; (void)bk; (void)bv;
#endif
}

// ---------------------------------------------------------------------------
// Pipelined tensor-core flash attention.
// smem: ctrl [0,64) | red [64,2112) | K bufs 2x64KB @4096 | V bufs 2x32KB.
// TMEM: QH 0 | QL 64 | PH 128 | PL 192 | S 256 | O 384.
// mbarS (sb+8): S-MMA commits; mbarPV (sb+16): PV commits. One outstanding each.
// ---------------------------------------------------------------------------
#define AT_KB(b) (4096 + (b)*65536)
#define AT_VB(b) (4096 + 131072 + (b)*32768)
#define TC_SMEM  (4096 + 131072 + 65536)    /* 200704 B */
#define TMC_QH 0
#define TMC_QL 64
#define TMC_PH 128
#define TMC_PL 192
#define TMC_S  256
#define TMC_O  384

__global__ __launch_bounds__(256, 1)
void attn_tc_kernel(float* __restrict__ out) {
#if HAS_TC
    extern __shared__ char smem[];
    const uint32_t sb = smem_u32(smem);
    const int tid = threadIdx.x;
    const int wid = tid >> 5, lid = tid & 31;
    const int chh = wid >> 2;
    const int irow = (wid & 3)*32 + lid;
    const uint32_t woff = (uint32_t)(wid & 3) << 21;
    const int bh = blockIdx.y;
    const int bb = bh >> 3, h = bh & 7;
    const int i0 = blockIdx.x * 128;

    float* red = (float*)(smem + 64);

    if (wid == 0) { TC_ALLOC(sb + 0, 512); TC_RELINQ(); }
    if (tid == 0) { MBAR_INIT(sb + 8, 1); MBAR_INIT(sb + 16, 1); }
    __syncthreads();
    uint32_t tmem;
    asm volatile("ld.shared.b32 %0, [%1];" : "=r"(tmem) : "r"(sb + 0));

    const size_t bq = (size_t)bb*NPIX*CH + h*DH;
    const size_t bo = ((size_t)bb*CH + h*DH)*NPIX;

    // K tile loader: [128 j][64 dims] x 4 regions (kh,kl,qh,ql) into buffer _b
    #define LOADK(_jt, _b) do {                                              \
        int _j0 = (_jt)*128;                                                 \
        _Pragma("unroll")                                                    \
        for (int it = 0; it < 16; it++) {                                    \
            int lin = tid + it*256;                                          \
            int reg = lin >> 10;                                             \
            int j   = (lin >> 3) & 127;                                      \
            int u   = lin & 7;                                               \
            int gj  = _j0 + j;                                               \
            uint4 v = make_uint4(0,0,0,0);                                   \
            if (gj < NPIX) {                                                 \
                size_t rb = bq + (size_t)gj*CH;                              \
                const __nv_bfloat16* src =                                   \
                    (reg == 0) ? &g_kh[rb] : (reg == 1) ? &g_kl[rb] :        \
                    (reg == 2) ? &g_qh[rb] : &g_ql[rb];                      \
                v = *(const uint4*)(src + u*8);                              \
            }                                                                \
            *(uint4*)(smem + AT_KB(_b) + reg*16384 + sw_off(j, u*16)) = v;   \
        }                                                                    \
    } while (0)

    // V tile loader: [64 d][64 j] x 4 regions into buffer _b
    #define LOADV(_jt, _b) do {                                              \
        int _j0 = (_jt)*128;                                                 \
        _Pragma("unroll")                                                    \
        for (int it = 0; it < 8; it++) {                                     \
            int lin = tid + it*256;                                          \
            int reg = lin >> 9;                                              \
            int d   = (lin >> 3) & 63;                                       \
            int u   = lin & 7;                                               \
            int jc  = reg >> 1;                                              \
            int hl  = reg & 1;                                               \
            int gjs = _j0 + jc*64 + u*8;                                     \
            uint4 v = make_uint4(0,0,0,0);                                   \
            const __nv_bfloat16* src = hl ? g_vol : g_voh;                   \
            src += bo + (size_t)d*NPIX;                                      \
            if (gjs + 7 < NPIX) {                                            \
                v = *(const uint4*)(src + gjs);                              \
            } else if (gjs < NPIX) {                                         \
                __nv_bfloat16 tmp[8];                                        \
                _Pragma("unroll")                                            \
                for (int e = 0; e < 8; e++)                                  \
                    tmp[e] = (gjs + e < NPIX) ? src[gjs + e] : __float2bfloat16(0.f); \
                v = *(const uint4*)tmp;                                      \
            }                                                                \
            *(uint4*)(smem + AT_VB(_b) + reg*8192 + sw_off(d, u*16)) = v;    \
        }                                                                    \
    } while (0)

    // S-MMA issue from K buffer _b (caller: wid==0, fenced, elected)
    #define ISSUE_S(_b) do {                                                 \
        _Pragma("unroll")                                                    \
        for (int s = 0; s < 8; s++) {                                        \
            int chunk = s >> 2;                                              \
            uint64_t bh_d = mkdesc_k(sb + AT_KB(_b) + chunk*32768) + (uint64_t)((s&3)*2); \
            uint64_t bl_d = mkdesc_k(sb + AT_KB(_b) + chunk*32768 + 16384) + (uint64_t)((s&3)*2); \
            uint32_t aH = tmem + TMC_QH + s*8;                               \
            uint32_t aL = tmem + TMC_QL + s*8;                               \
            mma_f16_ts(tmem + TMC_S, aH, bh_d, IDESC_128, s != 0);           \
            mma_f16_ts(tmem + TMC_S, aH, bl_d, IDESC_128, true);             \
            mma_f16_ts(tmem + TMC_S, aL, bh_d, IDESC_128, true);             \
        }                                                                    \
        TC_COMMIT(sb + 8);                                                   \
    } while (0)

    // PV-MMA issue from V buffer _b
    #define ISSUE_PV(_b) do {                                                \
        _Pragma("unroll")                                                    \
        for (int s = 0; s < 8; s++) {                                        \
            int chunk = s >> 2;                                              \
            uint64_t bh_d = mkdesc_k(sb + AT_VB(_b) + chunk*16384) + (uint64_t)((s&3)*2); \
            uint64_t bl_d = mkdesc_k(sb + AT_VB(_b) + chunk*16384 + 8192) + (uint64_t)((s&3)*2); \
            uint32_t aH = tmem + TMC_PH + s*8;                               \
            uint32_t aL = tmem + TMC_PL + s*8;                               \
            mma_f16_ts(tmem + TMC_O, aH, bh_d, IDESC_64, s != 0);            \
            mma_f16_ts(tmem + TMC_O, aH, bl_d, IDESC_64, true);              \
            mma_f16_ts(tmem + TMC_O, aL, bh_d, IDESC_64, true);              \
        }                                                                    \
        TC_COMMIT(sb + 16);                                                  \
    } while (0)

    // ---- prologue: Q -> TMEM; K(0),K(1),V(0) -> smem; issue S(0) ----
    {
        int gi = i0 + irow;
        uint32_t qr[32];
        const uint32_t* srcq = (chh == 0) ? (const uint32_t*)&g_qh[bq + (size_t)gi*CH]
                                          : (const uint32_t*)&g_ql[bq + (size_t)gi*CH];
        const uint32_t* srcp = (chh == 0) ? (const uint32_t*)&g_ph[((size_t)h*NPIX + gi)*DH]
                                          : (const uint32_t*)&g_pl[((size_t)h*NPIX + gi)*DH];
        uint32_t cb = (chh == 0) ? TMC_QH : TMC_QL;
        #pragma unroll
        for (int c = 0; c < 32; c++) qr[c] = (gi < NPIX) ? srcq[c] : 0u;
        STTM_X32(tmem + cb + woff, qr);
        #pragma unroll
        for (int c = 0; c < 32; c++) qr[c] = (gi < NPIX) ? srcp[c] : 0u;
        STTM_X32(tmem + cb + 32 + woff, qr);
        TC_WAIT_ST();
    }
    LOADK(0, 0);
    LOADK(1, 1);
    LOADV(0, 0);
    FENCE_ASYNC();
    TC_FENCE_BEFORE();
    __syncthreads();
    if (wid == 0) {
        TC_FENCE_AFTER();
        if (elect1()) ISSUE_S(0);    // mbarS count 0
    }

    float m = -INFINITY, l = 0.f;
    float o_acc[32];
    #pragma unroll
    for (int c = 0; c < 32; c++) o_acc[c] = 0.f;

    for (int jt = 0; jt < 7; jt++) {
        const int j0 = jt * 128;
        const int buf = jt & 1, nbuf = buf ^ 1;

        // 1. wait S(jt); 2. read S
        MBAR_WAIT(sb + 8, (uint32_t)(jt & 1));
        TC_FENCE_AFTER();
        float sv[64];
        {
            uint32_t rr[32];
            LDTM_X32(rr, tmem + TMC_S + chh*64);
            TC_WAIT_LD();
            #pragma unroll
            for (int c = 0; c < 32; c++) sv[c] = __uint_as_float(rr[c]);
            LDTM_X32(rr, tmem + TMC_S + chh*64 + 32);
            TC_WAIT_LD();
            #pragma unroll
            for (int c = 0; c < 32; c++) sv[32+c] = __uint_as_float(rr[c]);
        }
        TC_FENCE_BEFORE();
        __syncthreads();   // all warps done reading S region

        // 3. issue S(jt+1) — overlaps softmax below
        if (jt < 6 && wid == 0) {
            TC_FENCE_AFTER();
            if (elect1()) ISSUE_S(nbuf);   // mbarS count jt+1
        }

        // 4. online softmax
        float mx = -INFINITY;
        #pragma unroll
        for (int c = 0; c < 64; c++) {
            if (j0 + chh*64 + c >= NPIX) sv[c] = -INFINITY;
            mx = fmaxf(mx, sv[c]);
        }
        red[chh*128 + irow] = mx;
        __syncthreads();
        float mnew = fmaxf(m, fmaxf(red[irow], red[128 + irow]));
        float scale = __expf(m - mnew);
        m = mnew;
        float psum = 0.f;
        #pragma unroll
        for (int c = 0; c < 64; c++) {
            float p = __expf(sv[c] - mnew);
            sv[c] = p;
            psum += p;
        }
        red[256 + chh*128 + irow] = psum;
        __syncthreads();
        l = l*scale + red[256 + irow] + red[256 + 128 + irow];

        // 5. store P
        {
            uint32_t prh[32], prl[32];
            #pragma unroll
            for (int c = 0; c < 32; c++)
                split2(sv[2*c], sv[2*c+1], prh[c], prl[c]);
            STTM_X32(tmem + TMC_PH + chh*32 + woff, prh);
            STTM_X32(tmem + TMC_PL + chh*32 + woff, prl);
            TC_WAIT_ST();
        }
        TC_FENCE_BEFORE();
        __syncthreads();

        // 6. issue PV(jt)
        if (wid == 0) {
            TC_FENCE_AFTER();
            if (elect1()) ISSUE_PV(buf);   // mbarPV count jt
        }

        // 7. prefetch (overlaps PV exec): K(jt+2) into buf (freed by S(jt) wait),
        //    V(jt+1) into nbuf (freed by PV(jt-1) wait last iter)
        if (jt + 2 <= 6) LOADK(jt + 2, buf);
        if (jt + 1 <= 6) LOADV(jt + 1, nbuf);
        FENCE_ASYNC();
        TC_FENCE_BEFORE();

        // 8. wait PV(jt), accumulate O
        MBAR_WAIT(sb + 16, (uint32_t)(jt & 1));
        TC_FENCE_AFTER();
        {
            uint32_t po[32];
            LDTM_X32(po, tmem + TMC_O + chh*32);
            TC_WAIT_LD();
            TC_FENCE_BEFORE();
            #pragma unroll
            for (int c = 0; c < 32; c++)
                o_acc[c] = o_acc[c]*scale + __uint_as_float(po[c]);
        }
    }
    #undef LOADK
    #undef LOADV
    #undef ISSUE_S
    #undef ISSUE_PV

    // ---- epilogue: normalize, transpose via smem, coalesced store ----
    __syncthreads();
    float inv = __fdividef(1.f, l);
    float* Os = (float*)(smem + 4096);   // reuse K buf0: [d 64][i 128] stride 132
    #pragma unroll
    for (int c = 0; c < 32; c++)
        Os[(chh*32 + c)*132 + irow] = o_acc[c] * inv;
    __syncthreads();
    #pragma unroll
    for (int it = 0; it < 8; it++) {
        int lin = tid + it*256;
        int d = lin >> 5, i4 = (lin & 31)*4;
        int gi = i0 + i4;
        if (gi < NPIX) {
            float4 v = *(const float4*)&Os[d*132 + i4];
            *(float4*)&out[bo + (size_t)d*NPIX + gi] = v;
        }
    }
    __syncthreads();
    if (wid == 0) TC_DEALLOC(tmem, 512);
#else
    (void)out;
#endif
}

// ---------------------------------------------------------------------------
extern "C" void kernel_launch(void* const* d_in, const int* in_sizes, int n_in,
                              void* d_out, int out_size) {
    const float* x     = (const float*)d_in[0];
    const float* wq    = (const float*)d_in[1];
    const float* bq    = (const float*)d_in[2];
    const float* wk    = (const float*)d_in[3];
    const float* bk    = (const float*)d_in[4];
    const float* wv    = (const float*)d_in[5];
    const float* bv    = (const float*)d_in[6];
    const float* rel_h = (const float*)d_in[7];
    const float* rel_w = (const float*)d_in[8];
    float* out = (float*)d_out;

    cudaFuncSetAttribute(attn_tc_kernel,
                         cudaFuncAttributeMaxDynamicSharedMemorySize, TC_SMEM);
    cudaFuncSetAttribute(qkv_tc_kernel,
                         cudaFuncAttributeMaxDynamicSharedMemorySize, PROJ_SMEM);

    // prep
    dim3 xgrid((NPIX + 31)/32, CH/32, NB);
    split_x_kernel<<<xgrid, dim3(32, 8)>>>(x);
    split_w_kernel<<<(3*CH*CH + 255)/256, 256>>>(wq, wk, wv);
    pos_kernel<<<(HEADS*DH*NPIX + 255)/256, 256>>>(rel_h, rel_w);

    // merged tcgen05 QKV projection
    dim3 pgrid(7, 4, NB);
    qkv_tc_kernel<<<pgrid, 256, PROJ_SMEM>>>(bq, bk, bv);

    // pipelined tcgen05 attention
    dim3 tgrid(7, NB*HEADS);
    attn_tc_kernel<<<tgrid, 256, TC_SMEM>>>(out);
}